// round 1
// baseline (speedup 1.0000x reference)
#include <cuda_runtime.h>
#include <math.h>

#define B_TOT 2048   // 64 * 32 rows
#define S_DIM 2048
#define N_AG  32
#define EMB   64
#define NP    2304   // padded concatenated output cols (2240 -> 18*128)

// Scratch (device globals: no allocation allowed in kernel_launch)
__device__ float g_Wcat[S_DIM * NP];        // [K=2048][2304]: Ww1 | Wwf | Wb1 | Wv1 | pad0
__device__ float g_bcat[NP];
__device__ float g_Y[B_TOT * NP];           // st @ Wcat + bcat  (pre-abs, pre-nonlin)
__device__ float g_q1[B_TOT * N_AG];        // masked-mix outputs

// ---------------------------------------------------------------------------
// Pack weights into one concatenated [2048 x 2304] matrix (+ bias vector).
// ---------------------------------------------------------------------------
__global__ void pack_kernel(const float* __restrict__ Ww1, const float* __restrict__ bw1,
                            const float* __restrict__ Wwf, const float* __restrict__ bwf,
                            const float* __restrict__ Wb1, const float* __restrict__ bb1,
                            const float* __restrict__ Wv1, const float* __restrict__ bv1) {
    int idx = blockIdx.x * blockDim.x + threadIdx.x;
    int stride = gridDim.x * blockDim.x;
    if (idx < NP) {
        int n = idx;
        float bv;
        if (n < 2048)      bv = bw1[n];
        else if (n < 2112) bv = bwf[n - 2048];
        else if (n < 2176) bv = bb1[n - 2112];
        else if (n < 2240) bv = bv1[n - 2176];
        else               bv = 0.f;
        g_bcat[n] = bv;
    }
    for (int i = idx; i < S_DIM * NP; i += stride) {
        int k = i / NP, n = i - k * NP;
        float v;
        if (n < 2048)      v = Ww1[k * 2048 + n];
        else if (n < 2112) v = Wwf[k * 64 + (n - 2048)];
        else if (n < 2176) v = Wb1[k * 64 + (n - 2112)];
        else if (n < 2240) v = Wv1[k * 64 + (n - 2176)];
        else               v = 0.f;
        g_Wcat[i] = v;
    }
}

// ---------------------------------------------------------------------------
// K1: Y[2048 x 2304] = st[2048 x 2048] @ Wcat + bcat
// Classic 128x128x16 fp32 tile, 8x8 per thread, 256 threads.
// ---------------------------------------------------------------------------
__global__ __launch_bounds__(256) void gemm_kernel(const float* __restrict__ A) {
    __shared__ float As[16][132];   // transposed A tile, padded
    __shared__ float Bs[16][128];

    const int bm = blockIdx.y * 128;
    const int bn = blockIdx.x * 128;
    const int tid = threadIdx.x;
    const int tx = tid & 15;
    const int ty = tid >> 4;

    float acc[8][8];
#pragma unroll
    for (int i = 0; i < 8; i++)
#pragma unroll
        for (int j = 0; j < 8; j++) acc[i][j] = 0.f;

    const float* Ap = A + (size_t)bm * S_DIM;
    const float* Bp = g_Wcat + bn;

    for (int k0 = 0; k0 < S_DIM; k0 += 16) {
#pragma unroll
        for (int l = 0; l < 2; l++) {
            int i = tid + l * 256;          // float4 index, 512 total
            int r = i >> 2;                 // 4 float4 per row
            int c4 = i & 3;
            float4 v = *(const float4*)(Ap + (size_t)r * S_DIM + k0 + c4 * 4);
            As[c4 * 4 + 0][r] = v.x;
            As[c4 * 4 + 1][r] = v.y;
            As[c4 * 4 + 2][r] = v.z;
            As[c4 * 4 + 3][r] = v.w;
        }
#pragma unroll
        for (int l = 0; l < 2; l++) {
            int i = tid + l * 256;
            int r = i >> 5;                 // 32 float4 per row
            int c4 = i & 31;
            *(float4*)&Bs[r][c4 * 4] = *(const float4*)(Bp + (size_t)(k0 + r) * NP + c4 * 4);
        }
        __syncthreads();
#pragma unroll
        for (int kk = 0; kk < 16; kk++) {
            float af[8], bf[8];
            *(float4*)&af[0] = *(const float4*)&As[kk][ty * 8];
            *(float4*)&af[4] = *(const float4*)&As[kk][ty * 8 + 4];
            *(float4*)&bf[0] = *(const float4*)&Bs[kk][tx * 8];
            *(float4*)&bf[4] = *(const float4*)&Bs[kk][tx * 8 + 4];
#pragma unroll
            for (int i = 0; i < 8; i++)
#pragma unroll
                for (int j = 0; j < 8; j++) acc[i][j] = fmaf(af[i], bf[j], acc[i][j]);
        }
        __syncthreads();
    }

#pragma unroll
    for (int i = 0; i < 8; i++) {
        int r = bm + ty * 8 + i;
#pragma unroll
        for (int j = 0; j < 8; j += 4) {
            int c = bn + tx * 8 + j;
            float4 o;
            o.x = acc[i][j + 0] + g_bcat[c + 0];
            o.y = acc[i][j + 1] + g_bcat[c + 1];
            o.z = acc[i][j + 2] + g_bcat[c + 2];
            o.w = acc[i][j + 3] + g_bcat[c + 3];
            *(float4*)(g_Y + (size_t)r * NP + c) = o;
        }
    }
}

// ---------------------------------------------------------------------------
// K2 (fused): for (b-tile of 128, agent i) compute the rank-64 correction
//   C = st[:, i*64:(i+1)*64] @ Wcat[i*64:(i+1)*64, :]
// streamed in 64-column groups, consumed immediately into the masked mix:
//   q1[b,i] = hidden . w_final + v     (hidden/w_final/v built from Y - C)
// ---------------------------------------------------------------------------
__global__ __launch_bounds__(256) void corr_kernel(const float* __restrict__ st,
                                                   const float* __restrict__ qs,
                                                   const float* __restrict__ Wv2,
                                                   const float* __restrict__ bv2) {
    __shared__ float stc[128][64];   // st chunk tile [b][k]  (32 KB)
    __shared__ float Wg[64][64];     // current 64-col weight group (16 KB)

    const int bt0 = blockIdx.x * 128;
    const int ag  = blockIdx.y;
    const int tid = threadIdx.x;
    const int tx  = tid & 15;        // 16 cols of 4 -> e
    const int ty  = tid >> 4;        // 16 rows of 8 -> b

    // load st chunk: rows bt0..+127, cols ag*64..+63 (2048 float4, 8/thread)
#pragma unroll
    for (int l = 0; l < 8; l++) {
        int i = tid + l * 256;
        int r = i >> 4;
        int c4 = i & 15;
        float4 v = *(const float4*)(st + (size_t)(bt0 + r) * S_DIM + ag * 64 + c4 * 4);
        stc[r][c4 * 4 + 0] = v.x;
        stc[r][c4 * 4 + 1] = v.y;
        stc[r][c4 * 4 + 2] = v.z;
        stc[r][c4 * 4 + 3] = v.w;
    }

    float h[8][4];
#pragma unroll
    for (int i = 0; i < 8; i++)
#pragma unroll
        for (int j = 0; j < 4; j++) h[i][j] = 0.f;
    float wfm[8][4];
    float hid[8][4];
    float vp[8];
#pragma unroll
    for (int i = 0; i < 8; i++) vp[i] = 0.f;

    for (int g = 0; g < 35; g++) {
        __syncthreads();
        // load 64x64 weight group: rows ag*64+k, cols g*64+e
#pragma unroll
        for (int l = 0; l < 4; l++) {
            int i = tid + l * 256;
            int k = i >> 4;
            int c4 = i & 15;
            *(float4*)&Wg[k][c4 * 4] =
                *(const float4*)(g_Wcat + (size_t)(ag * 64 + k) * NP + g * 64 + c4 * 4);
        }
        __syncthreads();

        float C[8][4];
#pragma unroll
        for (int i = 0; i < 8; i++)
#pragma unroll
            for (int j = 0; j < 4; j++) C[i][j] = 0.f;

#pragma unroll 8
        for (int kk = 0; kk < 64; kk++) {
            float bf[4];
            *(float4*)bf = *(const float4*)&Wg[kk][tx * 4];
#pragma unroll
            for (int i = 0; i < 8; i++) {
                float a = stc[ty * 8 + i][kk];
#pragma unroll
                for (int j = 0; j < 4; j++) C[i][j] = fmaf(a, bf[j], C[i][j]);
            }
        }

        // consume the group
#pragma unroll
        for (int i = 0; i < 8; i++) {
            int b = bt0 + ty * 8 + i;
            float4 y = *(const float4*)(g_Y + (size_t)b * NP + g * 64 + tx * 4);
            float m0 = y.x - C[i][0];
            float m1 = y.y - C[i][1];
            float m2 = y.z - C[i][2];
            float m3 = y.w - C[i][3];
            if (g < 32) {                       // w1 groups (agent g)
                float q = qs[(size_t)b * N_AG + g];
                h[i][0] = fmaf(q, fabsf(m0), h[i][0]);
                h[i][1] = fmaf(q, fabsf(m1), h[i][1]);
                h[i][2] = fmaf(q, fabsf(m2), h[i][2]);
                h[i][3] = fmaf(q, fabsf(m3), h[i][3]);
            } else if (g == 32) {               // w_final
                wfm[i][0] = fabsf(m0);
                wfm[i][1] = fabsf(m1);
                wfm[i][2] = fabsf(m2);
                wfm[i][3] = fabsf(m3);
            } else if (g == 33) {               // b1 -> hidden = elu(h + b1m)
                float t0 = h[i][0] + m0; hid[i][0] = t0 > 0.f ? t0 : expm1f(t0);
                float t1 = h[i][1] + m1; hid[i][1] = t1 > 0.f ? t1 : expm1f(t1);
                float t2 = h[i][2] + m2; hid[i][2] = t2 > 0.f ? t2 : expm1f(t2);
                float t3 = h[i][3] + m3; hid[i][3] = t3 > 0.f ? t3 : expm1f(t3);
            } else {                            // v1 -> v partial
                vp[i] += fmaxf(m0, 0.f) * Wv2[tx * 4 + 0]
                       + fmaxf(m1, 0.f) * Wv2[tx * 4 + 1]
                       + fmaxf(m2, 0.f) * Wv2[tx * 4 + 2]
                       + fmaxf(m3, 0.f) * Wv2[tx * 4 + 3];
            }
        }
    }

    float bv2v = bv2[0];
#pragma unroll
    for (int i = 0; i < 8; i++) {
        float s = hid[i][0] * wfm[i][0] + hid[i][1] * wfm[i][1]
                + hid[i][2] * wfm[i][2] + hid[i][3] * wfm[i][3] + vp[i];
#pragma unroll
        for (int off = 8; off >= 1; off >>= 1)
            s += __shfl_xor_sync(0xffffffffu, s, off);
        if (tx == 0)
            g_q1[(size_t)(bt0 + ty * 8 + i) * N_AG + ag] = s + bv2v;
    }
}

// ---------------------------------------------------------------------------
// K3: per-row epilogue. Compute q_tot from Y, wc = normalize(|q_tot - q1|),
// then the final mix with qs*wc (reusing |Y| cached in smem). One block per b.
// ---------------------------------------------------------------------------
__global__ void final_kernel(const float* __restrict__ qs,
                             const float* __restrict__ Wv2,
                             const float* __restrict__ bv2,
                             float* __restrict__ out) {
    __shared__ float absY[2048];
    __shared__ float qs2[32];
    __shared__ float red[4];

    const int b = blockIdx.x;
    const int e = threadIdx.x;          // 0..63
    const int lane = e & 31, warp = e >> 5;
    const float* Yr = g_Y + (size_t)b * NP;

    float h = 0.f;
#pragma unroll
    for (int a = 0; a < 32; a++) {
        float v = fabsf(Yr[a * 64 + e]);
        absY[a * 64 + e] = v;
        h = fmaf(qs[(size_t)b * N_AG + a], v, h);
    }
    float wf = fabsf(Yr[2048 + e]);
    float b1 = Yr[2112 + e];
    float rv = fmaxf(Yr[2176 + e], 0.f) * Wv2[e];

    float t = h + b1;
    float hid = t > 0.f ? t : expm1f(t);
    float s = hid * wf;
    float sv = rv;
#pragma unroll
    for (int off = 16; off >= 1; off >>= 1) {
        s  += __shfl_xor_sync(0xffffffffu, s, off);
        sv += __shfl_xor_sync(0xffffffffu, sv, off);
    }
    if (lane == 0) { red[warp] = s; red[2 + warp] = sv; }
    __syncthreads();

    float vtot  = red[2] + red[3] + bv2[0];
    float q_tot = red[0] + red[1] + vtot;

    if (e < 32) {   // warp 0: wc
        float d = fabsf(q_tot - g_q1[(size_t)b * N_AG + e]);
        float d2 = d * d;
#pragma unroll
        for (int off = 16; off >= 1; off >>= 1)
            d2 += __shfl_xor_sync(0xffffffffu, d2, off);
        float nrm = fmaxf(sqrtf(d2), 1e-12f);
        qs2[e] = qs[(size_t)b * N_AG + e] * (d / nrm);
    }
    __syncthreads();

    float h2 = 0.f;
#pragma unroll
    for (int a = 0; a < 32; a++)
        h2 = fmaf(qs2[a], absY[a * 64 + e], h2);
    float t2 = h2 + b1;
    float hid2 = t2 > 0.f ? t2 : expm1f(t2);
    float s2 = hid2 * wf;
#pragma unroll
    for (int off = 16; off >= 1; off >>= 1)
        s2 += __shfl_xor_sync(0xffffffffu, s2, off);
    if (lane == 0) red[warp] = s2;
    __syncthreads();
    if (e == 0) out[b] = red[0] + red[1] + vtot;
}

// ---------------------------------------------------------------------------
extern "C" void kernel_launch(void* const* d_in, const int* in_sizes, int n_in,
                              void* d_out, int out_size) {
    const float* agent_qs = (const float*)d_in[0];
    const float* states   = (const float*)d_in[1];
    const float* Ww1 = (const float*)d_in[2];
    const float* bw1 = (const float*)d_in[3];
    const float* Wwf = (const float*)d_in[4];
    const float* bwf = (const float*)d_in[5];
    const float* Wb1 = (const float*)d_in[6];
    const float* bb1 = (const float*)d_in[7];
    const float* Wv1 = (const float*)d_in[8];
    const float* bv1 = (const float*)d_in[9];
    const float* Wv2 = (const float*)d_in[10];
    const float* bv2 = (const float*)d_in[11];
    float* out = (float*)d_out;

    pack_kernel<<<512, 256>>>(Ww1, bw1, Wwf, bwf, Wb1, bb1, Wv1, bv1);
    gemm_kernel<<<dim3(NP / 128, B_TOT / 128), 256>>>(states);
    corr_kernel<<<dim3(B_TOT / 128, N_AG), 256>>>(states, agent_qs, Wv2, bv2);
    final_kernel<<<B_TOT, 64>>>(agent_qs, Wv2, bv2, out);
}

// round 2
// speedup vs baseline: 1.0007x; 1.0007x over previous
#include <cuda_runtime.h>
#include <math.h>

#define B_TOT 2048   // 64 * 32 rows
#define S_DIM 2048
#define N_AG  32
#define EMB   64
#define NP    2304   // padded concatenated output cols (2240 -> 18*128)

// Scratch (device globals: no allocation allowed in kernel_launch)
__device__ float g_Wcat[S_DIM * NP];        // [K=2048][2304]: Ww1 | Wwf | Wb1 | Wv1 | pad0
__device__ float g_bcat[NP];
__device__ float g_Y[B_TOT * NP];           // st @ Wcat + bcat  (pre-abs, pre-nonlin)
__device__ float g_q1[B_TOT * N_AG];        // masked-mix outputs

// ---------------------------------------------------------------------------
// Pack weights into one concatenated [2048 x 2304] matrix (+ bias vector).
// ---------------------------------------------------------------------------
__global__ void pack_kernel(const float* __restrict__ Ww1, const float* __restrict__ bw1,
                            const float* __restrict__ Wwf, const float* __restrict__ bwf,
                            const float* __restrict__ Wb1, const float* __restrict__ bb1,
                            const float* __restrict__ Wv1, const float* __restrict__ bv1) {
    int idx = blockIdx.x * blockDim.x + threadIdx.x;
    int stride = gridDim.x * blockDim.x;
    if (idx < NP) {
        int n = idx;
        float bv;
        if (n < 2048)      bv = bw1[n];
        else if (n < 2112) bv = bwf[n - 2048];
        else if (n < 2176) bv = bb1[n - 2112];
        else if (n < 2240) bv = bv1[n - 2176];
        else               bv = 0.f;
        g_bcat[n] = bv;
    }
    for (int i = idx; i < S_DIM * NP; i += stride) {
        int k = i / NP, n = i - k * NP;
        float v;
        if (n < 2048)      v = Ww1[k * 2048 + n];
        else if (n < 2112) v = Wwf[k * 64 + (n - 2048)];
        else if (n < 2176) v = Wb1[k * 64 + (n - 2112)];
        else if (n < 2240) v = Wv1[k * 64 + (n - 2176)];
        else               v = 0.f;
        g_Wcat[i] = v;
    }
}

// ---------------------------------------------------------------------------
// K1: Y[2048 x 2304] = st[2048 x 2048] @ Wcat + bcat
// Classic 128x128x16 fp32 tile, 8x8 per thread, 256 threads.
// ---------------------------------------------------------------------------
__global__ __launch_bounds__(256) void gemm_kernel(const float* __restrict__ A) {
    __shared__ float As[16][132];   // transposed A tile, padded
    __shared__ float Bs[16][128];

    const int bm = blockIdx.y * 128;
    const int bn = blockIdx.x * 128;
    const int tid = threadIdx.x;
    const int tx = tid & 15;
    const int ty = tid >> 4;

    float acc[8][8];
#pragma unroll
    for (int i = 0; i < 8; i++)
#pragma unroll
        for (int j = 0; j < 8; j++) acc[i][j] = 0.f;

    const float* Ap = A + (size_t)bm * S_DIM;
    const float* Bp = g_Wcat + bn;

    for (int k0 = 0; k0 < S_DIM; k0 += 16) {
#pragma unroll
        for (int l = 0; l < 2; l++) {
            int i = tid + l * 256;          // float4 index, 512 total
            int r = i >> 2;                 // 4 float4 per row
            int c4 = i & 3;
            float4 v = *(const float4*)(Ap + (size_t)r * S_DIM + k0 + c4 * 4);
            As[c4 * 4 + 0][r] = v.x;
            As[c4 * 4 + 1][r] = v.y;
            As[c4 * 4 + 2][r] = v.z;
            As[c4 * 4 + 3][r] = v.w;
        }
#pragma unroll
        for (int l = 0; l < 2; l++) {
            int i = tid + l * 256;
            int r = i >> 5;                 // 32 float4 per row
            int c4 = i & 31;
            *(float4*)&Bs[r][c4 * 4] = *(const float4*)(Bp + (size_t)(k0 + r) * NP + c4 * 4);
        }
        __syncthreads();
#pragma unroll
        for (int kk = 0; kk < 16; kk++) {
            float af[8], bf[8];
            *(float4*)&af[0] = *(const float4*)&As[kk][ty * 8];
            *(float4*)&af[4] = *(const float4*)&As[kk][ty * 8 + 4];
            *(float4*)&bf[0] = *(const float4*)&Bs[kk][tx * 8];
            *(float4*)&bf[4] = *(const float4*)&Bs[kk][tx * 8 + 4];
#pragma unroll
            for (int i = 0; i < 8; i++)
#pragma unroll
                for (int j = 0; j < 8; j++) acc[i][j] = fmaf(af[i], bf[j], acc[i][j]);
        }
        __syncthreads();
    }

#pragma unroll
    for (int i = 0; i < 8; i++) {
        int r = bm + ty * 8 + i;
#pragma unroll
        for (int j = 0; j < 8; j += 4) {
            int c = bn + tx * 8 + j;
            float4 o;
            o.x = acc[i][j + 0] + g_bcat[c + 0];
            o.y = acc[i][j + 1] + g_bcat[c + 1];
            o.z = acc[i][j + 2] + g_bcat[c + 2];
            o.w = acc[i][j + 3] + g_bcat[c + 3];
            *(float4*)(g_Y + (size_t)r * NP + c) = o;
        }
    }
}

// ---------------------------------------------------------------------------
// K2 (fused): for (b-tile of 128, agent i) compute the rank-64 correction
//   C = st[:, i*64:(i+1)*64] @ Wcat[i*64:(i+1)*64, :]
// streamed in 64-column groups, consumed immediately into the masked mix:
//   q1[b,i] = hidden . w_final + v     (hidden/w_final/v built from Y - C)
// ---------------------------------------------------------------------------
__global__ __launch_bounds__(256) void corr_kernel(const float* __restrict__ st,
                                                   const float* __restrict__ qs,
                                                   const float* __restrict__ Wv2,
                                                   const float* __restrict__ bv2) {
    __shared__ float stc[128][64];   // st chunk tile [b][k]  (32 KB)
    __shared__ float Wg[64][64];     // current 64-col weight group (16 KB)

    const int bt0 = blockIdx.x * 128;
    const int ag  = blockIdx.y;
    const int tid = threadIdx.x;
    const int tx  = tid & 15;        // 16 cols of 4 -> e
    const int ty  = tid >> 4;        // 16 rows of 8 -> b

    // load st chunk: rows bt0..+127, cols ag*64..+63 (2048 float4, 8/thread)
#pragma unroll
    for (int l = 0; l < 8; l++) {
        int i = tid + l * 256;
        int r = i >> 4;
        int c4 = i & 15;
        float4 v = *(const float4*)(st + (size_t)(bt0 + r) * S_DIM + ag * 64 + c4 * 4);
        stc[r][c4 * 4 + 0] = v.x;
        stc[r][c4 * 4 + 1] = v.y;
        stc[r][c4 * 4 + 2] = v.z;
        stc[r][c4 * 4 + 3] = v.w;
    }

    float h[8][4];
#pragma unroll
    for (int i = 0; i < 8; i++)
#pragma unroll
        for (int j = 0; j < 4; j++) h[i][j] = 0.f;
    float wfm[8][4];
    float hid[8][4];
    float vp[8];
#pragma unroll
    for (int i = 0; i < 8; i++) vp[i] = 0.f;

    for (int g = 0; g < 35; g++) {
        __syncthreads();
        // load 64x64 weight group: rows ag*64+k, cols g*64+e
#pragma unroll
        for (int l = 0; l < 4; l++) {
            int i = tid + l * 256;
            int k = i >> 4;
            int c4 = i & 15;
            *(float4*)&Wg[k][c4 * 4] =
                *(const float4*)(g_Wcat + (size_t)(ag * 64 + k) * NP + g * 64 + c4 * 4);
        }
        __syncthreads();

        float C[8][4];
#pragma unroll
        for (int i = 0; i < 8; i++)
#pragma unroll
            for (int j = 0; j < 4; j++) C[i][j] = 0.f;

#pragma unroll 8
        for (int kk = 0; kk < 64; kk++) {
            float bf[4];
            *(float4*)bf = *(const float4*)&Wg[kk][tx * 4];
#pragma unroll
            for (int i = 0; i < 8; i++) {
                float a = stc[ty * 8 + i][kk];
#pragma unroll
                for (int j = 0; j < 4; j++) C[i][j] = fmaf(a, bf[j], C[i][j]);
            }
        }

        // consume the group
#pragma unroll
        for (int i = 0; i < 8; i++) {
            int b = bt0 + ty * 8 + i;
            float4 y = *(const float4*)(g_Y + (size_t)b * NP + g * 64 + tx * 4);
            float m0 = y.x - C[i][0];
            float m1 = y.y - C[i][1];
            float m2 = y.z - C[i][2];
            float m3 = y.w - C[i][3];
            if (g < 32) {                       // w1 groups (agent g)
                float q = qs[(size_t)b * N_AG + g];
                h[i][0] = fmaf(q, fabsf(m0), h[i][0]);
                h[i][1] = fmaf(q, fabsf(m1), h[i][1]);
                h[i][2] = fmaf(q, fabsf(m2), h[i][2]);
                h[i][3] = fmaf(q, fabsf(m3), h[i][3]);
            } else if (g == 32) {               // w_final
                wfm[i][0] = fabsf(m0);
                wfm[i][1] = fabsf(m1);
                wfm[i][2] = fabsf(m2);
                wfm[i][3] = fabsf(m3);
            } else if (g == 33) {               // b1 -> hidden = elu(h + b1m)
                float t0 = h[i][0] + m0; hid[i][0] = t0 > 0.f ? t0 : expm1f(t0);
                float t1 = h[i][1] + m1; hid[i][1] = t1 > 0.f ? t1 : expm1f(t1);
                float t2 = h[i][2] + m2; hid[i][2] = t2 > 0.f ? t2 : expm1f(t2);
                float t3 = h[i][3] + m3; hid[i][3] = t3 > 0.f ? t3 : expm1f(t3);
            } else {                            // v1 -> v partial
                vp[i] += fmaxf(m0, 0.f) * Wv2[tx * 4 + 0]
                       + fmaxf(m1, 0.f) * Wv2[tx * 4 + 1]
                       + fmaxf(m2, 0.f) * Wv2[tx * 4 + 2]
                       + fmaxf(m3, 0.f) * Wv2[tx * 4 + 3];
            }
        }
    }

    float bv2v = bv2[0];
#pragma unroll
    for (int i = 0; i < 8; i++) {
        float s = hid[i][0] * wfm[i][0] + hid[i][1] * wfm[i][1]
                + hid[i][2] * wfm[i][2] + hid[i][3] * wfm[i][3] + vp[i];
#pragma unroll
        for (int off = 8; off >= 1; off >>= 1)
            s += __shfl_xor_sync(0xffffffffu, s, off);
        if (tx == 0)
            g_q1[(size_t)(bt0 + ty * 8 + i) * N_AG + ag] = s + bv2v;
    }
}

// ---------------------------------------------------------------------------
// K3: per-row epilogue. Compute q_tot from Y, wc = normalize(|q_tot - q1|),
// then the final mix with qs*wc (reusing |Y| cached in smem). One block per b.
// ---------------------------------------------------------------------------
__global__ void final_kernel(const float* __restrict__ qs,
                             const float* __restrict__ Wv2,
                             const float* __restrict__ bv2,
                             float* __restrict__ out) {
    __shared__ float absY[2048];
    __shared__ float qs2[32];
    __shared__ float red[4];

    const int b = blockIdx.x;
    const int e = threadIdx.x;          // 0..63
    const int lane = e & 31, warp = e >> 5;
    const float* Yr = g_Y + (size_t)b * NP;

    float h = 0.f;
#pragma unroll
    for (int a = 0; a < 32; a++) {
        float v = fabsf(Yr[a * 64 + e]);
        absY[a * 64 + e] = v;
        h = fmaf(qs[(size_t)b * N_AG + a], v, h);
    }
    float wf = fabsf(Yr[2048 + e]);
    float b1 = Yr[2112 + e];
    float rv = fmaxf(Yr[2176 + e], 0.f) * Wv2[e];

    float t = h + b1;
    float hid = t > 0.f ? t : expm1f(t);
    float s = hid * wf;
    float sv = rv;
#pragma unroll
    for (int off = 16; off >= 1; off >>= 1) {
        s  += __shfl_xor_sync(0xffffffffu, s, off);
        sv += __shfl_xor_sync(0xffffffffu, sv, off);
    }
    if (lane == 0) { red[warp] = s; red[2 + warp] = sv; }
    __syncthreads();

    float vtot  = red[2] + red[3] + bv2[0];
    float q_tot = red[0] + red[1] + vtot;

    if (e < 32) {   // warp 0: wc
        float d = fabsf(q_tot - g_q1[(size_t)b * N_AG + e]);
        float d2 = d * d;
#pragma unroll
        for (int off = 16; off >= 1; off >>= 1)
            d2 += __shfl_xor_sync(0xffffffffu, d2, off);
        float nrm = fmaxf(sqrtf(d2), 1e-12f);
        qs2[e] = qs[(size_t)b * N_AG + e] * (d / nrm);
    }
    __syncthreads();

    float h2 = 0.f;
#pragma unroll
    for (int a = 0; a < 32; a++)
        h2 = fmaf(qs2[a], absY[a * 64 + e], h2);
    float t2 = h2 + b1;
    float hid2 = t2 > 0.f ? t2 : expm1f(t2);
    float s2 = hid2 * wf;
#pragma unroll
    for (int off = 16; off >= 1; off >>= 1)
        s2 += __shfl_xor_sync(0xffffffffu, s2, off);
    if (lane == 0) red[warp] = s2;
    __syncthreads();
    if (e == 0) out[b] = red[0] + red[1] + vtot;
}

// ---------------------------------------------------------------------------
extern "C" void kernel_launch(void* const* d_in, const int* in_sizes, int n_in,
                              void* d_out, int out_size) {
    const float* agent_qs = (const float*)d_in[0];
    const float* states   = (const float*)d_in[1];
    const float* Ww1 = (const float*)d_in[2];
    const float* bw1 = (const float*)d_in[3];
    const float* Wwf = (const float*)d_in[4];
    const float* bwf = (const float*)d_in[5];
    const float* Wb1 = (const float*)d_in[6];
    const float* bb1 = (const float*)d_in[7];
    const float* Wv1 = (const float*)d_in[8];
    const float* bv1 = (const float*)d_in[9];
    const float* Wv2 = (const float*)d_in[10];
    const float* bv2 = (const float*)d_in[11];
    float* out = (float*)d_out;

    pack_kernel<<<512, 256>>>(Ww1, bw1, Wwf, bwf, Wb1, bb1, Wv1, bv1);
    gemm_kernel<<<dim3(NP / 128, B_TOT / 128), 256>>>(states);
    corr_kernel<<<dim3(B_TOT / 128, N_AG), 256>>>(states, agent_qs, Wv2, bv2);
    final_kernel<<<B_TOT, 64>>>(agent_qs, Wv2, bv2, out);
}

// round 3
// speedup vs baseline: 2.7720x; 2.7701x over previous
#include <cuda_runtime.h>
#include <cuda_bf16.h>
#include <math.h>
#include <stdint.h>

#define B_TOT 2048   // 64 * 32 rows
#define S_DIM 2048
#define N_AG  32
#define EMB   64
#define NP    2304   // padded concatenated output cols (2240 -> 18*128)

// Scratch (device globals: no allocation allowed in kernel_launch)
__device__ __nv_bfloat16 g_Wh[S_DIM * NP];   // Wcat hi split
__device__ __nv_bfloat16 g_Wl[S_DIM * NP];   // Wcat lo split
__device__ __nv_bfloat16 g_Sh[B_TOT * S_DIM];// st hi split
__device__ __nv_bfloat16 g_Sl[B_TOT * S_DIM];// st lo split
__device__ float g_bcat[NP];
__device__ float g_Y[B_TOT * NP];            // st @ Wcat + bcat (fp32)
__device__ float g_q1[B_TOT * N_AG];         // masked-mix outputs

// ---------------------------------------------------------------------------
// MMA helpers (m16n8k16 bf16, fp32 accum)
// ---------------------------------------------------------------------------
__device__ __forceinline__ void ldsm_x4(uint32_t* r, const void* p) {
    uint32_t a = (uint32_t)__cvta_generic_to_shared(p);
    asm volatile("ldmatrix.sync.aligned.m8n8.x4.shared.b16 {%0,%1,%2,%3}, [%4];"
                 : "=r"(r[0]), "=r"(r[1]), "=r"(r[2]), "=r"(r[3]) : "r"(a));
}
__device__ __forceinline__ void ldsm_x4t(uint32_t* r, const void* p) {
    uint32_t a = (uint32_t)__cvta_generic_to_shared(p);
    asm volatile("ldmatrix.sync.aligned.m8n8.x4.trans.shared.b16 {%0,%1,%2,%3}, [%4];"
                 : "=r"(r[0]), "=r"(r[1]), "=r"(r[2]), "=r"(r[3]) : "r"(a));
}
__device__ __forceinline__ void mma_bf16(float* d, const uint32_t* a, const uint32_t* b) {
    asm volatile(
        "mma.sync.aligned.m16n8k16.row.col.f32.bf16.bf16.f32 "
        "{%0,%1,%2,%3},{%4,%5,%6,%7},{%8,%9},{%0,%1,%2,%3};"
        : "+f"(d[0]), "+f"(d[1]), "+f"(d[2]), "+f"(d[3])
        : "r"(a[0]), "r"(a[1]), "r"(a[2]), "r"(a[3]), "r"(b[0]), "r"(b[1]));
}

// ---------------------------------------------------------------------------
// Pack: concat weights, split everything into bf16 hi/lo pairs.
// ---------------------------------------------------------------------------
__device__ __forceinline__ void split2(float x, __nv_bfloat16& h, __nv_bfloat16& l) {
    __nv_bfloat16 hh = __float2bfloat16(x);
    h = hh;
    l = __float2bfloat16(x - __bfloat162float(hh));
}

__global__ void pack_kernel(const float* __restrict__ st,
                            const float* __restrict__ Ww1, const float* __restrict__ bw1,
                            const float* __restrict__ Wwf, const float* __restrict__ bwf,
                            const float* __restrict__ Wb1, const float* __restrict__ bb1,
                            const float* __restrict__ Wv1, const float* __restrict__ bv1) {
    int idx = blockIdx.x * blockDim.x + threadIdx.x;
    int stride = gridDim.x * blockDim.x;
    if (idx < NP) {
        int n = idx;
        float bv;
        if (n < 2048)      bv = bw1[n];
        else if (n < 2112) bv = bwf[n - 2048];
        else if (n < 2176) bv = bb1[n - 2112];
        else if (n < 2240) bv = bv1[n - 2176];
        else               bv = 0.f;
        g_bcat[n] = bv;
    }
    for (int i = idx; i < S_DIM * NP; i += stride) {
        int k = i / NP, n = i - k * NP;
        float v;
        if (n < 2048)      v = Ww1[k * 2048 + n];
        else if (n < 2112) v = Wwf[k * 64 + (n - 2048)];
        else if (n < 2176) v = Wb1[k * 64 + (n - 2112)];
        else if (n < 2240) v = Wv1[k * 64 + (n - 2176)];
        else               v = 0.f;
        split2(v, g_Wh[i], g_Wl[i]);
    }
    for (int i = idx; i < B_TOT * S_DIM; i += stride)
        split2(st[i], g_Sh[i], g_Sl[i]);
}

// ---------------------------------------------------------------------------
// K1: Y = st @ Wcat + bcat via bf16-split MMA (3 mma per accumulate step).
// Block 128x128, 8 warps (4m x 2n), warp tile 32x64. K-chunk 64.
// ---------------------------------------------------------------------------
#define K1_SMEM (36864 + 34816)
__global__ __launch_bounds__(256, 1) void gemm_mma(float* __restrict__ dummy) {
    extern __shared__ char smem[];
    __nv_bfloat16* Ah = (__nv_bfloat16*)smem;                 // [128][72]
    __nv_bfloat16* Al = (__nv_bfloat16*)(smem + 18432);
    __nv_bfloat16* Bh = (__nv_bfloat16*)(smem + 36864);       // [64][136]
    __nv_bfloat16* Bl = (__nv_bfloat16*)(smem + 54272);

    const int bn = blockIdx.x * 128;
    const int bm = blockIdx.y * 128;
    const int tid = threadIdx.x;
    const int lane = tid & 31;
    const int warp = tid >> 5;
    const int wm = warp & 3;     // 0..3 -> 32 rows each
    const int wn = warp >> 2;    // 0..1 -> 64 cols each

    float acc[2][8][4];
#pragma unroll
    for (int i = 0; i < 2; i++)
#pragma unroll
        for (int j = 0; j < 8; j++)
#pragma unroll
            for (int c = 0; c < 4; c++) acc[i][j][c] = 0.f;

    for (int k0 = 0; k0 < S_DIM; k0 += 64) {
#pragma unroll
        for (int l = 0; l < 4; l++) {
            int idx = l * 256 + tid;
            int r = idx >> 3, c8 = idx & 7;         // A: 128 rows x 8 uint4
            *(uint4*)&Ah[r * 72 + c8 * 8] =
                *(const uint4*)(g_Sh + (size_t)(bm + r) * S_DIM + k0 + c8 * 8);
            *(uint4*)&Al[r * 72 + c8 * 8] =
                *(const uint4*)(g_Sl + (size_t)(bm + r) * S_DIM + k0 + c8 * 8);
            int rb = idx >> 4, cb = idx & 15;       // B: 64 rows x 16 uint4
            *(uint4*)&Bh[rb * 136 + cb * 8] =
                *(const uint4*)(g_Wh + (size_t)(k0 + rb) * NP + bn + cb * 8);
            *(uint4*)&Bl[rb * 136 + cb * 8] =
                *(const uint4*)(g_Wl + (size_t)(k0 + rb) * NP + bn + cb * 8);
        }
        __syncthreads();

#pragma unroll
        for (int ks = 0; ks < 4; ks++) {
            uint32_t ah[2][4], al[2][4];
#pragma unroll
            for (int mf = 0; mf < 2; mf++) {
                const int ro = (wm * 32 + mf * 16 + (lane & 15)) * 72 + ks * 16 + (lane >> 4) * 8;
                ldsm_x4(ah[mf], &Ah[ro]);
                ldsm_x4(al[mf], &Al[ro]);
            }
            uint32_t bh[8][2], bl[8][2];
#pragma unroll
            for (int nq = 0; nq < 4; nq++) {
                const int bo = (ks * 16 + (lane & 15)) * 136 + wn * 64 + nq * 16 + (lane >> 4) * 8;
                uint32_t t[4];
                ldsm_x4t(t, &Bh[bo]);
                bh[nq * 2][0] = t[0]; bh[nq * 2][1] = t[1];
                bh[nq * 2 + 1][0] = t[2]; bh[nq * 2 + 1][1] = t[3];
                ldsm_x4t(t, &Bl[bo]);
                bl[nq * 2][0] = t[0]; bl[nq * 2][1] = t[1];
                bl[nq * 2 + 1][0] = t[2]; bl[nq * 2 + 1][1] = t[3];
            }
#pragma unroll
            for (int mf = 0; mf < 2; mf++)
#pragma unroll
                for (int nf = 0; nf < 8; nf++) {
                    mma_bf16(acc[mf][nf], ah[mf], bh[nf]);
                    mma_bf16(acc[mf][nf], ah[mf], bl[nf]);
                    mma_bf16(acc[mf][nf], al[mf], bh[nf]);
                }
        }
        __syncthreads();
    }

    // epilogue: add bias, store fp32 Y
#pragma unroll
    for (int mf = 0; mf < 2; mf++) {
        int r0 = bm + wm * 32 + mf * 16 + (lane >> 2);
#pragma unroll
        for (int nf = 0; nf < 8; nf++) {
            int c = bn + wn * 64 + nf * 8 + (lane & 3) * 2;
            float2 bc = *(const float2*)&g_bcat[c];
            float2 o0 = { acc[mf][nf][0] + bc.x, acc[mf][nf][1] + bc.y };
            float2 o1 = { acc[mf][nf][2] + bc.x, acc[mf][nf][3] + bc.y };
            *(float2*)(g_Y + (size_t)r0 * NP + c) = o0;
            *(float2*)(g_Y + (size_t)(r0 + 8) * NP + c) = o1;
        }
    }
}

// ---------------------------------------------------------------------------
// K2: fused rank-64 correction + masked mix via MMA.
// Block = (128-row tile, agent). 8 warps (4m x 2n), warp tile 32x32.
// Streams 35 column-groups of 64; correction consumed from MMA fragments.
// ---------------------------------------------------------------------------
#define K2_SMEM (36864 + 18432 + 16896 + 1024)
__global__ __launch_bounds__(256, 1) void corr_mma(const float* __restrict__ qs,
                                                   const float* __restrict__ Wv2,
                                                   const float* __restrict__ bv2) {
    extern __shared__ char smem[];
    __nv_bfloat16* Sh  = (__nv_bfloat16*)smem;                 // [128][72]
    __nv_bfloat16* Sl  = (__nv_bfloat16*)(smem + 18432);
    __nv_bfloat16* Wgh = (__nv_bfloat16*)(smem + 36864);       // [64][72]
    __nv_bfloat16* Wgl = (__nv_bfloat16*)(smem + 46080);
    float* qs_s        = (float*)(smem + 55296);               // [128][33]
    float* red         = (float*)(smem + 72192);               // [128][2]

    const int bt0 = blockIdx.x * 128;
    const int ag  = blockIdx.y;
    const int tid = threadIdx.x;
    const int lane = tid & 31;
    const int warp = tid >> 5;
    const int wm = warp & 3;     // 32 rows each
    const int wn = warp >> 2;    // 32 cols each

    // stage st chunk (hi/lo) and qs tile
#pragma unroll
    for (int l = 0; l < 4; l++) {
        int idx = l * 256 + tid;
        int r = idx >> 3, c8 = idx & 7;
        *(uint4*)&Sh[r * 72 + c8 * 8] =
            *(const uint4*)(g_Sh + (size_t)(bt0 + r) * S_DIM + ag * 64 + c8 * 8);
        *(uint4*)&Sl[r * 72 + c8 * 8] =
            *(const uint4*)(g_Sl + (size_t)(bt0 + r) * S_DIM + ag * 64 + c8 * 8);
    }
#pragma unroll
    for (int l = 0; l < 16; l++) {
        int idx = l * 256 + tid;       // 4096 floats
        int r = idx >> 5, c = idx & 31;
        qs_s[r * 33 + c] = qs[(size_t)(bt0 + r) * N_AG + c];
    }

    // per-thread row bases (4 row slots: mf*2 + rh)
    const int rloc0 = wm * 32 + (lane >> 2);
    float h[4][8];     // [slot][ecol]  accumulated mix pre-activation; becomes hidden
    float wfm[4][8];
    float vp[4] = {0.f, 0.f, 0.f, 0.f};
#pragma unroll
    for (int s = 0; s < 4; s++)
#pragma unroll
        for (int e = 0; e < 8; e++) h[s][e] = 0.f;

    // Wv2 values at this thread's e-columns
    float wv2r[8];
#pragma unroll
    for (int nf = 0; nf < 4; nf++) {
        int e = wn * 32 + nf * 8 + (lane & 3) * 2;
        wv2r[nf * 2]     = Wv2[e];
        wv2r[nf * 2 + 1] = Wv2[e + 1];
    }

    for (int g = 0; g < 35; g++) {
        __syncthreads();
#pragma unroll
        for (int l = 0; l < 2; l++) {
            int idx = l * 256 + tid;   // 512 uint4
            int r = idx >> 3, c8 = idx & 7;
            *(uint4*)&Wgh[r * 72 + c8 * 8] =
                *(const uint4*)(g_Wh + (size_t)(ag * 64 + r) * NP + g * 64 + c8 * 8);
            *(uint4*)&Wgl[r * 72 + c8 * 8] =
                *(const uint4*)(g_Wl + (size_t)(ag * 64 + r) * NP + g * 64 + c8 * 8);
        }
        __syncthreads();

        float c[2][4][4];
#pragma unroll
        for (int mf = 0; mf < 2; mf++)
#pragma unroll
            for (int nf = 0; nf < 4; nf++)
#pragma unroll
                for (int q = 0; q < 4; q++) c[mf][nf][q] = 0.f;

#pragma unroll
        for (int ks = 0; ks < 4; ks++) {
            uint32_t ah[2][4], al[2][4];
#pragma unroll
            for (int mf = 0; mf < 2; mf++) {
                const int ro = (wm * 32 + mf * 16 + (lane & 15)) * 72 + ks * 16 + (lane >> 4) * 8;
                ldsm_x4(ah[mf], &Sh[ro]);
                ldsm_x4(al[mf], &Sl[ro]);
            }
            uint32_t bh[4][2], bl[4][2];
#pragma unroll
            for (int nq = 0; nq < 2; nq++) {
                const int bo = (ks * 16 + (lane & 15)) * 72 + wn * 32 + nq * 16 + (lane >> 4) * 8;
                uint32_t t[4];
                ldsm_x4t(t, &Wgh[bo]);
                bh[nq * 2][0] = t[0]; bh[nq * 2][1] = t[1];
                bh[nq * 2 + 1][0] = t[2]; bh[nq * 2 + 1][1] = t[3];
                ldsm_x4t(t, &Wgl[bo]);
                bl[nq * 2][0] = t[0]; bl[nq * 2][1] = t[1];
                bl[nq * 2 + 1][0] = t[2]; bl[nq * 2 + 1][1] = t[3];
            }
#pragma unroll
            for (int mf = 0; mf < 2; mf++)
#pragma unroll
                for (int nf = 0; nf < 4; nf++) {
                    mma_bf16(c[mf][nf], ah[mf], bh[nf]);
                    mma_bf16(c[mf][nf], ah[mf], bl[nf]);
                    mma_bf16(c[mf][nf], al[mf], bh[nf]);
                }
        }

        // consume group: masked value m = Y - C
        float qv[4];
        if (g < 32) {
#pragma unroll
            for (int s = 0; s < 4; s++) {
                int rl = rloc0 + (s >> 1) * 16 + (s & 1) * 8;
                qv[s] = qs_s[rl * 33 + g];
            }
        }
#pragma unroll
        for (int mf = 0; mf < 2; mf++) {
            int r0 = bt0 + wm * 32 + mf * 16 + (lane >> 2);
#pragma unroll
            for (int nf = 0; nf < 4; nf++) {
                int col = g * 64 + wn * 32 + nf * 8 + (lane & 3) * 2;
                float2 y0 = *(const float2*)(g_Y + (size_t)r0 * NP + col);
                float2 y1 = *(const float2*)(g_Y + (size_t)(r0 + 8) * NP + col);
                float m00 = y0.x - c[mf][nf][0];
                float m01 = y0.y - c[mf][nf][1];
                float m10 = y1.x - c[mf][nf][2];
                float m11 = y1.y - c[mf][nf][3];
                int s0 = mf * 2, s1 = mf * 2 + 1;
                int e0 = nf * 2, e1 = nf * 2 + 1;
                if (g < 32) {
                    h[s0][e0] = fmaf(qv[s0], fabsf(m00), h[s0][e0]);
                    h[s0][e1] = fmaf(qv[s0], fabsf(m01), h[s0][e1]);
                    h[s1][e0] = fmaf(qv[s1], fabsf(m10), h[s1][e0]);
                    h[s1][e1] = fmaf(qv[s1], fabsf(m11), h[s1][e1]);
                } else if (g == 32) {           // w_final
                    wfm[s0][e0] = fabsf(m00);
                    wfm[s0][e1] = fabsf(m01);
                    wfm[s1][e0] = fabsf(m10);
                    wfm[s1][e1] = fabsf(m11);
                } else if (g == 33) {           // b1 -> hidden = elu(h + b1)
                    float t;
                    t = h[s0][e0] + m00; h[s0][e0] = t > 0.f ? t : expm1f(t);
                    t = h[s0][e1] + m01; h[s0][e1] = t > 0.f ? t : expm1f(t);
                    t = h[s1][e0] + m10; h[s1][e0] = t > 0.f ? t : expm1f(t);
                    t = h[s1][e1] + m11; h[s1][e1] = t > 0.f ? t : expm1f(t);
                } else {                        // v1 -> v partial
                    vp[s0] = fmaf(fmaxf(m00, 0.f), wv2r[e0], vp[s0]);
                    vp[s0] = fmaf(fmaxf(m01, 0.f), wv2r[e1], vp[s0]);
                    vp[s1] = fmaf(fmaxf(m10, 0.f), wv2r[e0], vp[s1]);
                    vp[s1] = fmaf(fmaxf(m11, 0.f), wv2r[e1], vp[s1]);
                }
            }
        }
    }

    // reduce: s[slot] = sum_e hidden*wfm + vp
    float sv[4];
#pragma unroll
    for (int s = 0; s < 4; s++) {
        float acc = vp[s];
#pragma unroll
        for (int e = 0; e < 8; e++) acc = fmaf(h[s][e], wfm[s][e], acc);
        acc += __shfl_xor_sync(0xffffffffu, acc, 1);
        acc += __shfl_xor_sync(0xffffffffu, acc, 2);
        sv[s] = acc;
    }
    if ((lane & 3) == 0) {
#pragma unroll
        for (int s = 0; s < 4; s++) {
            int rl = rloc0 + (s >> 1) * 16 + (s & 1) * 8;
            red[rl * 2 + wn] = sv[s];
        }
    }
    __syncthreads();
    if (tid < 128) {
        g_q1[(size_t)(bt0 + tid) * N_AG + ag] = red[tid * 2] + red[tid * 2 + 1] + bv2[0];
    }
}

// ---------------------------------------------------------------------------
// K3: per-row epilogue (unchanged): q_tot, wc normalize, final mix.
// ---------------------------------------------------------------------------
__global__ void final_kernel(const float* __restrict__ qs,
                             const float* __restrict__ Wv2,
                             const float* __restrict__ bv2,
                             float* __restrict__ out) {
    __shared__ float absY[2048];
    __shared__ float qs2[32];
    __shared__ float red[4];

    const int b = blockIdx.x;
    const int e = threadIdx.x;          // 0..63
    const int lane = e & 31, warp = e >> 5;
    const float* Yr = g_Y + (size_t)b * NP;

    float h = 0.f;
#pragma unroll
    for (int a = 0; a < 32; a++) {
        float v = fabsf(Yr[a * 64 + e]);
        absY[a * 64 + e] = v;
        h = fmaf(qs[(size_t)b * N_AG + a], v, h);
    }
    float wf = fabsf(Yr[2048 + e]);
    float b1 = Yr[2112 + e];
    float rv = fmaxf(Yr[2176 + e], 0.f) * Wv2[e];

    float t = h + b1;
    float hid = t > 0.f ? t : expm1f(t);
    float s = hid * wf;
    float sv = rv;
#pragma unroll
    for (int off = 16; off >= 1; off >>= 1) {
        s  += __shfl_xor_sync(0xffffffffu, s, off);
        sv += __shfl_xor_sync(0xffffffffu, sv, off);
    }
    if (lane == 0) { red[warp] = s; red[2 + warp] = sv; }
    __syncthreads();

    float vtot  = red[2] + red[3] + bv2[0];
    float q_tot = red[0] + red[1] + vtot;

    if (e < 32) {
        float d = fabsf(q_tot - g_q1[(size_t)b * N_AG + e]);
        float d2 = d * d;
#pragma unroll
        for (int off = 16; off >= 1; off >>= 1)
            d2 += __shfl_xor_sync(0xffffffffu, d2, off);
        float nrm = fmaxf(sqrtf(d2), 1e-12f);
        qs2[e] = qs[(size_t)b * N_AG + e] * (d / nrm);
    }
    __syncthreads();

    float h2 = 0.f;
#pragma unroll
    for (int a = 0; a < 32; a++)
        h2 = fmaf(qs2[a], absY[a * 64 + e], h2);
    float t2 = h2 + b1;
    float hid2 = t2 > 0.f ? t2 : expm1f(t2);
    float s2 = hid2 * wf;
#pragma unroll
    for (int off = 16; off >= 1; off >>= 1)
        s2 += __shfl_xor_sync(0xffffffffu, s2, off);
    if (lane == 0) red[warp] = s2;
    __syncthreads();
    if (e == 0) out[b] = red[0] + red[1] + vtot;
}

// ---------------------------------------------------------------------------
extern "C" void kernel_launch(void* const* d_in, const int* in_sizes, int n_in,
                              void* d_out, int out_size) {
    const float* agent_qs = (const float*)d_in[0];
    const float* states   = (const float*)d_in[1];
    const float* Ww1 = (const float*)d_in[2];
    const float* bw1 = (const float*)d_in[3];
    const float* Wwf = (const float*)d_in[4];
    const float* bwf = (const float*)d_in[5];
    const float* Wb1 = (const float*)d_in[6];
    const float* bb1 = (const float*)d_in[7];
    const float* Wv1 = (const float*)d_in[8];
    const float* bv1 = (const float*)d_in[9];
    const float* Wv2 = (const float*)d_in[10];
    const float* bv2 = (const float*)d_in[11];
    float* out = (float*)d_out;

    static bool attr_done = false;
    if (!attr_done) {
        cudaFuncSetAttribute(gemm_mma, cudaFuncAttributeMaxDynamicSharedMemorySize, K1_SMEM);
        cudaFuncSetAttribute(corr_mma, cudaFuncAttributeMaxDynamicSharedMemorySize, K2_SMEM);
        attr_done = true;
    }

    pack_kernel<<<1024, 256>>>(states, Ww1, bw1, Wwf, bwf, Wb1, bb1, Wv1, bv1);
    gemm_mma<<<dim3(NP / 128, B_TOT / 128), 256, K1_SMEM>>>(nullptr);
    corr_mma<<<dim3(B_TOT / 128, N_AG), 256, K2_SMEM>>>(agent_qs, Wv2, bv2);
    final_kernel<<<B_TOT, 64>>>(agent_qs, Wv2, bv2, out);
}

// round 5
// speedup vs baseline: 3.2678x; 1.1788x over previous
#include <cuda_runtime.h>
#include <cuda_bf16.h>
#include <cuda_fp16.h>
#include <math.h>
#include <stdint.h>

#define B_TOT 2048   // 64 * 32 rows
#define S_DIM 2048
#define N_AG  32
#define EMB   64
#define NP    2304   // padded concatenated output cols (2240 -> 18*128)

// Scratch (device globals: no allocation allowed in kernel_launch)
__device__ __nv_bfloat16 g_Wh[S_DIM * NP];   // Wcat hi split [K][N]
__device__ __nv_bfloat16 g_Wl[S_DIM * NP];   // Wcat lo split [K][N]
__device__ __half        g_Wf[S_DIM * NP];   // Wcat fp16 (for K2 single-mma correction)
__device__ __nv_bfloat16 g_Sh[B_TOT * S_DIM];// st hi split
__device__ __nv_bfloat16 g_Sl[B_TOT * S_DIM];// st lo split
__device__ __half        g_Sf[B_TOT * S_DIM];// st fp16
__device__ float g_bcat[NP];
__device__ float g_Y[B_TOT * NP];            // st @ Wcat + bcat (fp32)
__device__ float g_q1[B_TOT * N_AG];         // masked-mix outputs

// ---------------------------------------------------------------------------
// MMA helpers
// ---------------------------------------------------------------------------
__device__ __forceinline__ void ldsm_x4(uint32_t* r, const void* p) {
    uint32_t a = (uint32_t)__cvta_generic_to_shared(p);
    asm volatile("ldmatrix.sync.aligned.m8n8.x4.shared.b16 {%0,%1,%2,%3}, [%4];"
                 : "=r"(r[0]), "=r"(r[1]), "=r"(r[2]), "=r"(r[3]) : "r"(a));
}
__device__ __forceinline__ void ldsm_x4t(uint32_t* r, const void* p) {
    uint32_t a = (uint32_t)__cvta_generic_to_shared(p);
    asm volatile("ldmatrix.sync.aligned.m8n8.x4.trans.shared.b16 {%0,%1,%2,%3}, [%4];"
                 : "=r"(r[0]), "=r"(r[1]), "=r"(r[2]), "=r"(r[3]) : "r"(a));
}
__device__ __forceinline__ void mma_bf16(float* d, const uint32_t* a, const uint32_t* b) {
    asm volatile(
        "mma.sync.aligned.m16n8k16.row.col.f32.bf16.bf16.f32 "
        "{%0,%1,%2,%3},{%4,%5,%6,%7},{%8,%9},{%0,%1,%2,%3};"
        : "+f"(d[0]), "+f"(d[1]), "+f"(d[2]), "+f"(d[3])
        : "r"(a[0]), "r"(a[1]), "r"(a[2]), "r"(a[3]), "r"(b[0]), "r"(b[1]));
}
__device__ __forceinline__ void mma_fp16(float* d, const uint32_t* a, const uint32_t* b) {
    asm volatile(
        "mma.sync.aligned.m16n8k16.row.col.f32.f16.f16.f32 "
        "{%0,%1,%2,%3},{%4,%5,%6,%7},{%8,%9},{%0,%1,%2,%3};"
        : "+f"(d[0]), "+f"(d[1]), "+f"(d[2]), "+f"(d[3])
        : "r"(a[0]), "r"(a[1]), "r"(a[2]), "r"(a[3]), "r"(b[0]), "r"(b[1]));
}

__device__ __forceinline__ void split2(float x, __nv_bfloat16& h, __nv_bfloat16& l) {
    __nv_bfloat16 hh = __float2bfloat16(x);
    h = hh;
    l = __float2bfloat16(x - __bfloat162float(hh));
}

// ---------------------------------------------------------------------------
// Pack: concat weights, bf16 hi/lo splits + fp16 copies, bias.
// ---------------------------------------------------------------------------
__global__ void pack_kernel(const float* __restrict__ st,
                            const float* __restrict__ Ww1, const float* __restrict__ bw1,
                            const float* __restrict__ Wwf, const float* __restrict__ bwf,
                            const float* __restrict__ Wb1, const float* __restrict__ bb1,
                            const float* __restrict__ Wv1, const float* __restrict__ bv1) {
    int idx = blockIdx.x * blockDim.x + threadIdx.x;
    int stride = gridDim.x * blockDim.x;
    if (idx < NP) {
        int n = idx;
        float bv;
        if (n < 2048)      bv = bw1[n];
        else if (n < 2112) bv = bwf[n - 2048];
        else if (n < 2176) bv = bb1[n - 2112];
        else if (n < 2240) bv = bv1[n - 2176];
        else               bv = 0.f;
        g_bcat[n] = bv;
    }
    for (int i = idx; i < S_DIM * NP; i += stride) {
        int k = i / NP, n = i - k * NP;
        float v;
        if (n < 2048)      v = Ww1[k * 2048 + n];
        else if (n < 2112) v = Wwf[k * 64 + (n - 2048)];
        else if (n < 2176) v = Wb1[k * 64 + (n - 2112)];
        else if (n < 2240) v = Wv1[k * 64 + (n - 2176)];
        else               v = 0.f;
        split2(v, g_Wh[i], g_Wl[i]);
        g_Wf[i] = __float2half(v);
    }
    for (int i = idx; i < B_TOT * S_DIM; i += stride) {
        float v = st[i];
        split2(v, g_Sh[i], g_Sl[i]);
        g_Sf[i] = __float2half(v);
    }
}

// ---------------------------------------------------------------------------
// K1: Y = st @ Wcat + bcat via bf16-split MMA (3 mma per accumulate step).
// Block 128x128, 8 warps (4m x 2n), warp tile 32x64. K-chunk 64.
// ---------------------------------------------------------------------------
#define K1_SMEM (36864 + 34816)
__global__ __launch_bounds__(256, 1) void gemm_mma() {
    extern __shared__ char smem[];
    __nv_bfloat16* Ah = (__nv_bfloat16*)smem;                 // [128][72]
    __nv_bfloat16* Al = (__nv_bfloat16*)(smem + 18432);
    __nv_bfloat16* Bh = (__nv_bfloat16*)(smem + 36864);       // [64][136]
    __nv_bfloat16* Bl = (__nv_bfloat16*)(smem + 54272);

    const int bn = blockIdx.x * 128;
    const int bm = blockIdx.y * 128;
    const int tid = threadIdx.x;
    const int lane = tid & 31;
    const int warp = tid >> 5;
    const int wm = warp & 3;
    const int wn = warp >> 2;

    float acc[2][8][4];
#pragma unroll
    for (int i = 0; i < 2; i++)
#pragma unroll
        for (int j = 0; j < 8; j++)
#pragma unroll
            for (int c = 0; c < 4; c++) acc[i][j][c] = 0.f;

    for (int k0 = 0; k0 < S_DIM; k0 += 64) {
#pragma unroll
        for (int l = 0; l < 4; l++) {
            int idx = l * 256 + tid;
            int r = idx >> 3, c8 = idx & 7;
            *(uint4*)&Ah[r * 72 + c8 * 8] =
                *(const uint4*)(g_Sh + (size_t)(bm + r) * S_DIM + k0 + c8 * 8);
            *(uint4*)&Al[r * 72 + c8 * 8] =
                *(const uint4*)(g_Sl + (size_t)(bm + r) * S_DIM + k0 + c8 * 8);
            int rb = idx >> 4, cb = idx & 15;
            *(uint4*)&Bh[rb * 136 + cb * 8] =
                *(const uint4*)(g_Wh + (size_t)(k0 + rb) * NP + bn + cb * 8);
            *(uint4*)&Bl[rb * 136 + cb * 8] =
                *(const uint4*)(g_Wl + (size_t)(k0 + rb) * NP + bn + cb * 8);
        }
        __syncthreads();

#pragma unroll
        for (int ks = 0; ks < 4; ks++) {
            uint32_t ah[2][4], al[2][4];
#pragma unroll
            for (int mf = 0; mf < 2; mf++) {
                const int ro = (wm * 32 + mf * 16 + (lane & 15)) * 72 + ks * 16 + (lane >> 4) * 8;
                ldsm_x4(ah[mf], &Ah[ro]);
                ldsm_x4(al[mf], &Al[ro]);
            }
            uint32_t bh[8][2], bl[8][2];
#pragma unroll
            for (int nq = 0; nq < 4; nq++) {
                const int bo = (ks * 16 + (lane & 15)) * 136 + wn * 64 + nq * 16 + (lane >> 4) * 8;
                uint32_t t[4];
                ldsm_x4t(t, &Bh[bo]);
                bh[nq * 2][0] = t[0]; bh[nq * 2][1] = t[1];
                bh[nq * 2 + 1][0] = t[2]; bh[nq * 2 + 1][1] = t[3];
                ldsm_x4t(t, &Bl[bo]);
                bl[nq * 2][0] = t[0]; bl[nq * 2][1] = t[1];
                bl[nq * 2 + 1][0] = t[2]; bl[nq * 2 + 1][1] = t[3];
            }
#pragma unroll
            for (int mf = 0; mf < 2; mf++)
#pragma unroll
                for (int nf = 0; nf < 8; nf++) {
                    mma_bf16(acc[mf][nf], ah[mf], bh[nf]);
                    mma_bf16(acc[mf][nf], ah[mf], bl[nf]);
                    mma_bf16(acc[mf][nf], al[mf], bh[nf]);
                }
        }
        __syncthreads();
    }

#pragma unroll
    for (int mf = 0; mf < 2; mf++) {
        int r0 = bm + wm * 32 + mf * 16 + (lane >> 2);
#pragma unroll
        for (int nf = 0; nf < 8; nf++) {
            int c = bn + wn * 64 + nf * 8 + (lane & 3) * 2;
            float2 bc = *(const float2*)&g_bcat[c];
            float2 o0 = { acc[mf][nf][0] + bc.x, acc[mf][nf][1] + bc.y };
            float2 o1 = { acc[mf][nf][2] + bc.x, acc[mf][nf][3] + bc.y };
            *(float2*)(g_Y + (size_t)r0 * NP + c) = o0;
            *(float2*)(g_Y + (size_t)(r0 + 8) * NP + c) = o1;
        }
    }
}

// ---------------------------------------------------------------------------
// K2: fused rank-64 correction + masked mix. Single fp16 MMA per step
// (correction precision budget allows it), register-prefetch double buffer
// on the 64x64 weight group (one sync per group).
// ---------------------------------------------------------------------------
#define K2_SMEM (18432 + 18432 + 16896 + 1024)
__global__ __launch_bounds__(256, 1) void corr_mma(const float* __restrict__ qs,
                                                   const float* __restrict__ Wv2,
                                                   const float* __restrict__ bv2) {
    extern __shared__ char smem[];
    __half* Sf  = (__half*)smem;                  // [128][72]
    __half* Wgf = (__half*)(smem + 18432);        // [2][64][72]
    float* qs_s = (float*)(smem + 36864);         // [128][33]
    float* red  = (float*)(smem + 53760);         // [128][2]

    const int bt0 = blockIdx.x * 128;
    const int ag  = blockIdx.y;
    const int tid = threadIdx.x;
    const int lane = tid & 31;
    const int warp = tid >> 5;
    const int wm = warp & 3;
    const int wn = warp >> 2;

#pragma unroll
    for (int l = 0; l < 4; l++) {
        int idx = l * 256 + tid;
        int r = idx >> 3, c8 = idx & 7;
        *(uint4*)&Sf[r * 72 + c8 * 8] =
            *(const uint4*)(g_Sf + (size_t)(bt0 + r) * S_DIM + ag * 64 + c8 * 8);
    }
#pragma unroll
    for (int l = 0; l < 16; l++) {
        int idx = l * 256 + tid;
        int r = idx >> 5, c = idx & 31;
        qs_s[r * 33 + c] = qs[(size_t)(bt0 + r) * N_AG + c];
    }

    uint4 wf_r[2];
    auto loadW = [&](int g) {
#pragma unroll
        for (int l = 0; l < 2; l++) {
            int idx = l * 256 + tid;
            int r = idx >> 3, c8 = idx & 7;
            wf_r[l] = *(const uint4*)(g_Wf + (size_t)(ag * 64 + r) * NP + g * 64 + c8 * 8);
        }
    };
    auto storeW = [&](int b) {
#pragma unroll
        for (int l = 0; l < 2; l++) {
            int idx = l * 256 + tid;
            int r = idx >> 3, c8 = idx & 7;
            *(uint4*)&Wgf[b * 4608 + r * 72 + c8 * 8] = wf_r[l];
        }
    };
    loadW(0);
    storeW(0);

    const int rloc0 = wm * 32 + (lane >> 2);
    float h[4][8];
    float wfm[4][8];
    float vp[4] = {0.f, 0.f, 0.f, 0.f};
#pragma unroll
    for (int s = 0; s < 4; s++)
#pragma unroll
        for (int e = 0; e < 8; e++) h[s][e] = 0.f;

    float wv2r[8];
#pragma unroll
    for (int nf = 0; nf < 4; nf++) {
        int e = wn * 32 + nf * 8 + (lane & 3) * 2;
        wv2r[nf * 2]     = Wv2[e];
        wv2r[nf * 2 + 1] = Wv2[e + 1];
    }

    for (int g = 0; g < 35; g++) {
        __syncthreads();
        if (g < 34) loadW(g + 1);

        const __half* WgfB = Wgf + (g & 1) * 4608;

        float c[2][4][4];
#pragma unroll
        for (int mf = 0; mf < 2; mf++)
#pragma unroll
            for (int nf = 0; nf < 4; nf++)
#pragma unroll
                for (int q = 0; q < 4; q++) c[mf][nf][q] = 0.f;

#pragma unroll
        for (int ks = 0; ks < 4; ks++) {
            uint32_t af[2][4];
#pragma unroll
            for (int mf = 0; mf < 2; mf++) {
                const int ro = (wm * 32 + mf * 16 + (lane & 15)) * 72 + ks * 16 + (lane >> 4) * 8;
                ldsm_x4(af[mf], &Sf[ro]);
            }
            uint32_t bf[4][2];
#pragma unroll
            for (int nq = 0; nq < 2; nq++) {
                const int bo = (ks * 16 + (lane & 15)) * 72 + wn * 32 + nq * 16 + (lane >> 4) * 8;
                uint32_t t[4];
                ldsm_x4t(t, &WgfB[bo]);
                bf[nq * 2][0] = t[0]; bf[nq * 2][1] = t[1];
                bf[nq * 2 + 1][0] = t[2]; bf[nq * 2 + 1][1] = t[3];
            }
#pragma unroll
            for (int mf = 0; mf < 2; mf++)
#pragma unroll
                for (int nf = 0; nf < 4; nf++)
                    mma_fp16(c[mf][nf], af[mf], bf[nf]);
        }

        float qv[4];
        if (g < 32) {
#pragma unroll
            for (int s = 0; s < 4; s++) {
                int rl = rloc0 + (s >> 1) * 16 + (s & 1) * 8;
                qv[s] = qs_s[rl * 33 + g];
            }
        }
#pragma unroll
        for (int mf = 0; mf < 2; mf++) {
            int r0 = bt0 + wm * 32 + mf * 16 + (lane >> 2);
#pragma unroll
            for (int nf = 0; nf < 4; nf++) {
                int col = g * 64 + wn * 32 + nf * 8 + (lane & 3) * 2;
                float2 y0 = *(const float2*)(g_Y + (size_t)r0 * NP + col);
                float2 y1 = *(const float2*)(g_Y + (size_t)(r0 + 8) * NP + col);
                float m00 = y0.x - c[mf][nf][0];
                float m01 = y0.y - c[mf][nf][1];
                float m10 = y1.x - c[mf][nf][2];
                float m11 = y1.y - c[mf][nf][3];
                int s0 = mf * 2, s1 = mf * 2 + 1;
                int e0 = nf * 2, e1 = nf * 2 + 1;
                if (g < 32) {
                    h[s0][e0] = fmaf(qv[s0], fabsf(m00), h[s0][e0]);
                    h[s0][e1] = fmaf(qv[s0], fabsf(m01), h[s0][e1]);
                    h[s1][e0] = fmaf(qv[s1], fabsf(m10), h[s1][e0]);
                    h[s1][e1] = fmaf(qv[s1], fabsf(m11), h[s1][e1]);
                } else if (g == 32) {
                    wfm[s0][e0] = fabsf(m00);
                    wfm[s0][e1] = fabsf(m01);
                    wfm[s1][e0] = fabsf(m10);
                    wfm[s1][e1] = fabsf(m11);
                } else if (g == 33) {
                    float t;
                    t = h[s0][e0] + m00; h[s0][e0] = t > 0.f ? t : expm1f(t);
                    t = h[s0][e1] + m01; h[s0][e1] = t > 0.f ? t : expm1f(t);
                    t = h[s1][e0] + m10; h[s1][e0] = t > 0.f ? t : expm1f(t);
                    t = h[s1][e1] + m11; h[s1][e1] = t > 0.f ? t : expm1f(t);
                } else {
                    vp[s0] = fmaf(fmaxf(m00, 0.f), wv2r[e0], vp[s0]);
                    vp[s0] = fmaf(fmaxf(m01, 0.f), wv2r[e1], vp[s0]);
                    vp[s1] = fmaf(fmaxf(m10, 0.f), wv2r[e0], vp[s1]);
                    vp[s1] = fmaf(fmaxf(m11, 0.f), wv2r[e1], vp[s1]);
                }
            }
        }
        if (g < 34) storeW((g + 1) & 1);
    }

    float sv[4];
#pragma unroll
    for (int s = 0; s < 4; s++) {
        float acc = vp[s];
#pragma unroll
        for (int e = 0; e < 8; e++) acc = fmaf(h[s][e], wfm[s][e], acc);
        acc += __shfl_xor_sync(0xffffffffu, acc, 1);
        acc += __shfl_xor_sync(0xffffffffu, acc, 2);
        sv[s] = acc;
    }
    if ((lane & 3) == 0) {
#pragma unroll
        for (int s = 0; s < 4; s++) {
            int rl = rloc0 + (s >> 1) * 16 + (s & 1) * 8;
            red[rl * 2 + wn] = sv[s];
        }
    }
    __syncthreads();
    if (tid < 128)
        g_q1[(size_t)(bt0 + tid) * N_AG + ag] = red[tid * 2] + red[tid * 2 + 1] + bv2[0];
}

// ---------------------------------------------------------------------------
// K3: per-row epilogue (unchanged)
// ---------------------------------------------------------------------------
__global__ void final_kernel(const float* __restrict__ qs,
                             const float* __restrict__ Wv2,
                             const float* __restrict__ bv2,
                             float* __restrict__ out) {
    __shared__ float absY[2048];
    __shared__ float qs2[32];
    __shared__ float red[4];

    const int b = blockIdx.x;
    const int e = threadIdx.x;
    const int lane = e & 31, warp = e >> 5;
    const float* Yr = g_Y + (size_t)b * NP;

    float h = 0.f;
#pragma unroll
    for (int a = 0; a < 32; a++) {
        float v = fabsf(Yr[a * 64 + e]);
        absY[a * 64 + e] = v;
        h = fmaf(qs[(size_t)b * N_AG + a], v, h);
    }
    float wf = fabsf(Yr[2048 + e]);
    float b1 = Yr[2112 + e];
    float rv = fmaxf(Yr[2176 + e], 0.f) * Wv2[e];

    float t = h + b1;
    float hid = t > 0.f ? t : expm1f(t);
    float s = hid * wf;
    float sv = rv;
#pragma unroll
    for (int off = 16; off >= 1; off >>= 1) {
        s  += __shfl_xor_sync(0xffffffffu, s, off);
        sv += __shfl_xor_sync(0xffffffffu, sv, off);
    }
    if (lane == 0) { red[warp] = s; red[2 + warp] = sv; }
    __syncthreads();

    float vtot  = red[2] + red[3] + bv2[0];
    float q_tot = red[0] + red[1] + vtot;

    if (e < 32) {
        float d = fabsf(q_tot - g_q1[(size_t)b * N_AG + e]);
        float d2 = d * d;
#pragma unroll
        for (int off = 16; off >= 1; off >>= 1)
            d2 += __shfl_xor_sync(0xffffffffu, d2, off);
        float nrm = fmaxf(sqrtf(d2), 1e-12f);
        qs2[e] = qs[(size_t)b * N_AG + e] * (d / nrm);
    }
    __syncthreads();

    float h2 = 0.f;
#pragma unroll
    for (int a = 0; a < 32; a++)
        h2 = fmaf(qs2[a], absY[a * 64 + e], h2);
    float t2 = h2 + b1;
    float hid2 = t2 > 0.f ? t2 : expm1f(t2);
    float s2 = hid2 * wf;
#pragma unroll
    for (int off = 16; off >= 1; off >>= 1)
        s2 += __shfl_xor_sync(0xffffffffu, s2, off);
    if (lane == 0) red[warp] = s2;
    __syncthreads();
    if (e == 0) out[b] = red[0] + red[1] + vtot;
}

// ---------------------------------------------------------------------------
extern "C" void kernel_launch(void* const* d_in, const int* in_sizes, int n_in,
                              void* d_out, int out_size) {
    const float* agent_qs = (const float*)d_in[0];
    const float* states   = (const float*)d_in[1];
    const float* Ww1 = (const float*)d_in[2];
    const float* bw1 = (const float*)d_in[3];
    const float* Wwf = (const float*)d_in[4];
    const float* bwf = (const float*)d_in[5];
    const float* Wb1 = (const float*)d_in[6];
    const float* bb1 = (const float*)d_in[7];
    const float* Wv1 = (const float*)d_in[8];
    const float* bv1 = (const float*)d_in[9];
    const float* Wv2 = (const float*)d_in[10];
    const float* bv2 = (const float*)d_in[11];
    float* out = (float*)d_out;

    static bool attr_done = false;
    if (!attr_done) {
        cudaFuncSetAttribute(gemm_mma, cudaFuncAttributeMaxDynamicSharedMemorySize, K1_SMEM);
        cudaFuncSetAttribute(corr_mma, cudaFuncAttributeMaxDynamicSharedMemorySize, K2_SMEM);
        attr_done = true;
    }

    pack_kernel<<<1024, 256>>>(states, Ww1, bw1, Wwf, bwf, Wb1, bb1, Wv1, bv1);
    gemm_mma<<<dim3(NP / 128, B_TOT / 128), 256, K1_SMEM>>>();
    corr_mma<<<dim3(B_TOT / 128, N_AG), 256, K2_SMEM>>>(agent_qs, Wv2, bv2);
    final_kernel<<<B_TOT, 64>>>(agent_qs, Wv2, bv2, out);
}

// round 6
// speedup vs baseline: 3.9635x; 1.2129x over previous
#include <cuda_runtime.h>
#include <cuda_fp16.h>
#include <math.h>
#include <stdint.h>

#define B_TOT 2048   // 64 * 32 rows
#define S_DIM 2048
#define N_AG  32
#define EMB   64
#define NP    2304   // padded concatenated output cols (2240 -> 18*128)
#define KSCALE 32.0f
#define KINV   0.03125f

// Scratch (device globals: no allocation allowed in kernel_launch)
__device__ __half g_Wh[S_DIM * NP];    // Wcat fp16 hi  [K][N]
__device__ __half g_Ws[S_DIM * NP];    // Wcat fp16 (h + 32*l)
__device__ __half g_Sh[B_TOT * S_DIM]; // st fp16 hi
__device__ __half g_Ss[B_TOT * S_DIM]; // st fp16 (h + 32*l)
__device__ float g_bcat[NP];
__device__ float g_Y[B_TOT * NP];      // st @ Wcat + bcat (fp32)
__device__ float g_q1[B_TOT * N_AG];   // masked-mix outputs

// ---------------------------------------------------------------------------
// helpers
// ---------------------------------------------------------------------------
__device__ __forceinline__ void ldsm_x4(uint32_t* r, const void* p) {
    uint32_t a = (uint32_t)__cvta_generic_to_shared(p);
    asm volatile("ldmatrix.sync.aligned.m8n8.x4.shared.b16 {%0,%1,%2,%3}, [%4];"
                 : "=r"(r[0]), "=r"(r[1]), "=r"(r[2]), "=r"(r[3]) : "r"(a));
}
__device__ __forceinline__ void ldsm_x4t(uint32_t* r, const void* p) {
    uint32_t a = (uint32_t)__cvta_generic_to_shared(p);
    asm volatile("ldmatrix.sync.aligned.m8n8.x4.trans.shared.b16 {%0,%1,%2,%3}, [%4];"
                 : "=r"(r[0]), "=r"(r[1]), "=r"(r[2]), "=r"(r[3]) : "r"(a));
}
__device__ __forceinline__ void mma_fp16(float* d, const uint32_t* a, const uint32_t* b) {
    asm volatile(
        "mma.sync.aligned.m16n8k16.row.col.f32.f16.f16.f32 "
        "{%0,%1,%2,%3},{%4,%5,%6,%7},{%8,%9},{%0,%1,%2,%3};"
        : "+f"(d[0]), "+f"(d[1]), "+f"(d[2]), "+f"(d[3])
        : "r"(a[0]), "r"(a[1]), "r"(a[2]), "r"(a[3]), "r"(b[0]), "r"(b[1]));
}
__device__ __forceinline__ void cp16(uint32_t dst, const void* src) {
    asm volatile("cp.async.cg.shared.global [%0], [%1], 16;" :: "r"(dst), "l"(src));
}
#define CP_COMMIT()  asm volatile("cp.async.commit_group;" ::: "memory")
#define CP_WAIT(n)   asm volatile("cp.async.wait_group %0;" :: "n"(n) : "memory")

__device__ __forceinline__ void splitk(float x, __half& h, __half& s) {
    __half hh = __float2half(x);
    float hf = __half2float(hh);
    h = hh;
    s = __float2half(hf + KSCALE * (x - hf));
}

// ---------------------------------------------------------------------------
// Pack: concat weights, fp16 Karatsuba splits for W and st, bias.
// ---------------------------------------------------------------------------
__global__ void pack_kernel(const float* __restrict__ st,
                            const float* __restrict__ Ww1, const float* __restrict__ bw1,
                            const float* __restrict__ Wwf, const float* __restrict__ bwf,
                            const float* __restrict__ Wb1, const float* __restrict__ bb1,
                            const float* __restrict__ Wv1, const float* __restrict__ bv1) {
    int idx = blockIdx.x * blockDim.x + threadIdx.x;
    int stride = gridDim.x * blockDim.x;
    if (idx < NP) {
        int n = idx;
        float bv;
        if (n < 2048)      bv = bw1[n];
        else if (n < 2112) bv = bwf[n - 2048];
        else if (n < 2176) bv = bb1[n - 2112];
        else if (n < 2240) bv = bv1[n - 2176];
        else               bv = 0.f;
        g_bcat[n] = bv;
    }
    for (int i = idx; i < S_DIM * NP; i += stride) {
        int k = i / NP, n = i - k * NP;
        float v;
        if (n < 2048)      v = Ww1[k * 2048 + n];
        else if (n < 2112) v = Wwf[k * 64 + (n - 2048)];
        else if (n < 2176) v = Wb1[k * 64 + (n - 2112)];
        else if (n < 2240) v = Wv1[k * 64 + (n - 2176)];
        else               v = 0.f;
        splitk(v, g_Wh[i], g_Ws[i]);
    }
    for (int i = idx; i < B_TOT * S_DIM; i += stride)
        splitk(st[i], g_Sh[i], g_Ss[i]);
}

// ---------------------------------------------------------------------------
// K1: Y = st @ Wcat + bcat via fp16 Karatsuba (2 MMAs per step):
//   D1 = h.h', D2 = S.S',  Y = D1 + (D2 - D1)/32.
// Block 128x128, 8 warps (4m x 2n), K-chunk 64, cp.async double buffer.
// ---------------------------------------------------------------------------
#define K1_OFF_AH 0
#define K1_OFF_AS 18432
#define K1_OFF_BH 36864
#define K1_OFF_BS 54272
#define K1_BUF    71680
#define K1_SMEM   (2 * K1_BUF)

__global__ __launch_bounds__(256, 1) void gemm_ka() {
    extern __shared__ char smem[];
    const uint32_t sbase = (uint32_t)__cvta_generic_to_shared(smem);

    const int bn = blockIdx.x * 128;
    const int bm = blockIdx.y * 128;
    const int tid = threadIdx.x;
    const int lane = tid & 31;
    const int warp = tid >> 5;
    const int wm = warp & 3;
    const int wn = warp >> 2;

    // per-thread load coordinates (fixed across chunks)
    const int ra  = tid >> 3,  ca = tid & 7;     // A: +l*32 rows
    const int rb  = tid >> 4,  cb = tid & 15;    // B: +l*16 rows

    auto issue = [&](int c, int bufi) {
        const int k0 = c * 64;
        const uint32_t bb = sbase + bufi * K1_BUF;
#pragma unroll
        for (int l = 0; l < 4; l++) {
            int r = ra + l * 32;
            uint32_t off = (uint32_t)r * 144 + ca * 16;
            const __half* srcA = g_Sh + (size_t)(bm + r) * S_DIM + k0 + ca * 8;
            const __half* srcAs = g_Ss + (size_t)(bm + r) * S_DIM + k0 + ca * 8;
            cp16(bb + K1_OFF_AH + off, srcA);
            cp16(bb + K1_OFF_AS + off, srcAs);
            int rr = rb + l * 16;
            uint32_t offb = (uint32_t)rr * 272 + cb * 16;
            const __half* srcB = g_Wh + (size_t)(k0 + rr) * NP + bn + cb * 8;
            const __half* srcBs = g_Ws + (size_t)(k0 + rr) * NP + bn + cb * 8;
            cp16(bb + K1_OFF_BH + offb, srcB);
            cp16(bb + K1_OFF_BS + offb, srcBs);
        }
    };

    float d1[2][8][4], d2[2][8][4];
#pragma unroll
    for (int i = 0; i < 2; i++)
#pragma unroll
        for (int j = 0; j < 8; j++)
#pragma unroll
            for (int c = 0; c < 4; c++) { d1[i][j][c] = 0.f; d2[i][j][c] = 0.f; }

    issue(0, 0);
    CP_COMMIT();

    for (int c = 0; c < 32; c++) {
        const int bufi = c & 1;
        char* base = smem + bufi * K1_BUF;
        __half* Ah = (__half*)(base + K1_OFF_AH);
        __half* As = (__half*)(base + K1_OFF_AS);
        __half* Bh = (__half*)(base + K1_OFF_BH);
        __half* Bs = (__half*)(base + K1_OFF_BS);

        if (c < 31) {
            issue(c + 1, bufi ^ 1);
            CP_COMMIT();
            CP_WAIT(1);
        } else {
            CP_WAIT(0);
        }
        __syncthreads();

#pragma unroll
        for (int ks = 0; ks < 4; ks++) {
            uint32_t ah[2][4], as[2][4];
#pragma unroll
            for (int mf = 0; mf < 2; mf++) {
                const int ro = (wm * 32 + mf * 16 + (lane & 15)) * 72 + ks * 16 + (lane >> 4) * 8;
                ldsm_x4(ah[mf], &Ah[ro]);
                ldsm_x4(as[mf], &As[ro]);
            }
            uint32_t bh[8][2], bs[8][2];
#pragma unroll
            for (int nq = 0; nq < 4; nq++) {
                const int bo = (ks * 16 + (lane & 15)) * 136 + wn * 64 + nq * 16 + (lane >> 4) * 8;
                uint32_t t[4];
                ldsm_x4t(t, &Bh[bo]);
                bh[nq * 2][0] = t[0]; bh[nq * 2][1] = t[1];
                bh[nq * 2 + 1][0] = t[2]; bh[nq * 2 + 1][1] = t[3];
                ldsm_x4t(t, &Bs[bo]);
                bs[nq * 2][0] = t[0]; bs[nq * 2][1] = t[1];
                bs[nq * 2 + 1][0] = t[2]; bs[nq * 2 + 1][1] = t[3];
            }
#pragma unroll
            for (int mf = 0; mf < 2; mf++)
#pragma unroll
                for (int nf = 0; nf < 8; nf++) {
                    mma_fp16(d1[mf][nf], ah[mf], bh[nf]);
                    mma_fp16(d2[mf][nf], as[mf], bs[nf]);
                }
        }
        __syncthreads();
    }

    // epilogue: Y = d1 + (d2 - d1)/32 + bias
#pragma unroll
    for (int mf = 0; mf < 2; mf++) {
        int r0 = bm + wm * 32 + mf * 16 + (lane >> 2);
#pragma unroll
        for (int nf = 0; nf < 8; nf++) {
            int c = bn + wn * 64 + nf * 8 + (lane & 3) * 2;
            float2 bc = *(const float2*)&g_bcat[c];
            float2 o0, o1;
            o0.x = d1[mf][nf][0] + (d2[mf][nf][0] - d1[mf][nf][0]) * KINV + bc.x;
            o0.y = d1[mf][nf][1] + (d2[mf][nf][1] - d1[mf][nf][1]) * KINV + bc.y;
            o1.x = d1[mf][nf][2] + (d2[mf][nf][2] - d1[mf][nf][2]) * KINV + bc.x;
            o1.y = d1[mf][nf][3] + (d2[mf][nf][3] - d1[mf][nf][3]) * KINV + bc.y;
            *(float2*)(g_Y + (size_t)r0 * NP + c) = o0;
            *(float2*)(g_Y + (size_t)(r0 + 8) * NP + c) = o1;
        }
    }
}

// ---------------------------------------------------------------------------
// K2: fused rank-64 correction + masked mix. Single fp16 MMA per step,
// register-prefetch on weight group AND on the Y tile (hides L2 latency).
// ---------------------------------------------------------------------------
#define K2_SMEM (18432 + 18432 + 16896 + 1024)
__global__ __launch_bounds__(256, 1) void corr_mma(const float* __restrict__ qs,
                                                   const float* __restrict__ Wv2,
                                                   const float* __restrict__ bv2) {
    extern __shared__ char smem[];
    __half* Sf  = (__half*)smem;                  // [128][72]
    __half* Wgf = (__half*)(smem + 18432);        // [2][64][72]
    float* qs_s = (float*)(smem + 36864);         // [128][33]
    float* red  = (float*)(smem + 53760);         // [128][2]

    const int bt0 = blockIdx.x * 128;
    const int ag  = blockIdx.y;
    const int tid = threadIdx.x;
    const int lane = tid & 31;
    const int warp = tid >> 5;
    const int wm = warp & 3;
    const int wn = warp >> 2;

#pragma unroll
    for (int l = 0; l < 4; l++) {
        int idx = l * 256 + tid;
        int r = idx >> 3, c8 = idx & 7;
        *(uint4*)&Sf[r * 72 + c8 * 8] =
            *(const uint4*)(g_Sh + (size_t)(bt0 + r) * S_DIM + ag * 64 + c8 * 8);
    }
#pragma unroll
    for (int l = 0; l < 16; l++) {
        int idx = l * 256 + tid;
        int r = idx >> 5, c = idx & 31;
        qs_s[r * 33 + c] = qs[(size_t)(bt0 + r) * N_AG + c];
    }

    uint4 wf_r[2];
    auto loadW = [&](int g) {
#pragma unroll
        for (int l = 0; l < 2; l++) {
            int idx = l * 256 + tid;
            int r = idx >> 3, c8 = idx & 7;
            wf_r[l] = *(const uint4*)(g_Wh + (size_t)(ag * 64 + r) * NP + g * 64 + c8 * 8);
        }
    };
    auto storeW = [&](int b) {
#pragma unroll
        for (int l = 0; l < 2; l++) {
            int idx = l * 256 + tid;
            int r = idx >> 3, c8 = idx & 7;
            *(uint4*)&Wgf[b * 4608 + r * 72 + c8 * 8] = wf_r[l];
        }
    };
    loadW(0);
    storeW(0);

    const int rloc0 = wm * 32 + (lane >> 2);
    float h[4][8];
    float wfm[4][8];
    float vp[4] = {0.f, 0.f, 0.f, 0.f};
#pragma unroll
    for (int s = 0; s < 4; s++)
#pragma unroll
        for (int e = 0; e < 8; e++) h[s][e] = 0.f;

    float wv2r[8];
#pragma unroll
    for (int nf = 0; nf < 4; nf++) {
        int e = wn * 32 + nf * 8 + (lane & 3) * 2;
        wv2r[nf * 2]     = Wv2[e];
        wv2r[nf * 2 + 1] = Wv2[e + 1];
    }

    const int yr0 = bt0 + wm * 32 + (lane >> 2);

    for (int g = 0; g < 35; g++) {
        __syncthreads();
        if (g < 34) loadW(g + 1);

        // prefetch the Y tile for this group (L2 latency hides under MMAs)
        float2 yv0[2][4], yv1[2][4];
#pragma unroll
        for (int mf = 0; mf < 2; mf++) {
            int r0 = yr0 + mf * 16;
#pragma unroll
            for (int nf = 0; nf < 4; nf++) {
                int col = g * 64 + wn * 32 + nf * 8 + (lane & 3) * 2;
                yv0[mf][nf] = *(const float2*)(g_Y + (size_t)r0 * NP + col);
                yv1[mf][nf] = *(const float2*)(g_Y + (size_t)(r0 + 8) * NP + col);
            }
        }

        const __half* WgfB = Wgf + (g & 1) * 4608;

        float c[2][4][4];
#pragma unroll
        for (int mf = 0; mf < 2; mf++)
#pragma unroll
            for (int nf = 0; nf < 4; nf++)
#pragma unroll
                for (int q = 0; q < 4; q++) c[mf][nf][q] = 0.f;

#pragma unroll
        for (int ks = 0; ks < 4; ks++) {
            uint32_t af[2][4];
#pragma unroll
            for (int mf = 0; mf < 2; mf++) {
                const int ro = (wm * 32 + mf * 16 + (lane & 15)) * 72 + ks * 16 + (lane >> 4) * 8;
                ldsm_x4(af[mf], &Sf[ro]);
            }
            uint32_t bf[4][2];
#pragma unroll
            for (int nq = 0; nq < 2; nq++) {
                const int bo = (ks * 16 + (lane & 15)) * 72 + wn * 32 + nq * 16 + (lane >> 4) * 8;
                uint32_t t[4];
                ldsm_x4t(t, &WgfB[bo]);
                bf[nq * 2][0] = t[0]; bf[nq * 2][1] = t[1];
                bf[nq * 2 + 1][0] = t[2]; bf[nq * 2 + 1][1] = t[3];
            }
#pragma unroll
            for (int mf = 0; mf < 2; mf++)
#pragma unroll
                for (int nf = 0; nf < 4; nf++)
                    mma_fp16(c[mf][nf], af[mf], bf[nf]);
        }

        float qv[4];
        if (g < 32) {
#pragma unroll
            for (int s = 0; s < 4; s++) {
                int rl = rloc0 + (s >> 1) * 16 + (s & 1) * 8;
                qv[s] = qs_s[rl * 33 + g];
            }
        }
#pragma unroll
        for (int mf = 0; mf < 2; mf++) {
#pragma unroll
            for (int nf = 0; nf < 4; nf++) {
                float m00 = yv0[mf][nf].x - c[mf][nf][0];
                float m01 = yv0[mf][nf].y - c[mf][nf][1];
                float m10 = yv1[mf][nf].x - c[mf][nf][2];
                float m11 = yv1[mf][nf].y - c[mf][nf][3];
                int s0 = mf * 2, s1 = mf * 2 + 1;
                int e0 = nf * 2, e1 = nf * 2 + 1;
                if (g < 32) {
                    h[s0][e0] = fmaf(qv[s0], fabsf(m00), h[s0][e0]);
                    h[s0][e1] = fmaf(qv[s0], fabsf(m01), h[s0][e1]);
                    h[s1][e0] = fmaf(qv[s1], fabsf(m10), h[s1][e0]);
                    h[s1][e1] = fmaf(qv[s1], fabsf(m11), h[s1][e1]);
                } else if (g == 32) {
                    wfm[s0][e0] = fabsf(m00);
                    wfm[s0][e1] = fabsf(m01);
                    wfm[s1][e0] = fabsf(m10);
                    wfm[s1][e1] = fabsf(m11);
                } else if (g == 33) {
                    float t;
                    t = h[s0][e0] + m00; h[s0][e0] = t > 0.f ? t : expm1f(t);
                    t = h[s0][e1] + m01; h[s0][e1] = t > 0.f ? t : expm1f(t);
                    t = h[s1][e0] + m10; h[s1][e0] = t > 0.f ? t : expm1f(t);
                    t = h[s1][e1] + m11; h[s1][e1] = t > 0.f ? t : expm1f(t);
                } else {
                    vp[s0] = fmaf(fmaxf(m00, 0.f), wv2r[e0], vp[s0]);
                    vp[s0] = fmaf(fmaxf(m01, 0.f), wv2r[e1], vp[s0]);
                    vp[s1] = fmaf(fmaxf(m10, 0.f), wv2r[e0], vp[s1]);
                    vp[s1] = fmaf(fmaxf(m11, 0.f), wv2r[e1], vp[s1]);
                }
            }
        }
        if (g < 34) storeW((g + 1) & 1);
    }

    float sv[4];
#pragma unroll
    for (int s = 0; s < 4; s++) {
        float acc = vp[s];
#pragma unroll
        for (int e = 0; e < 8; e++) acc = fmaf(h[s][e], wfm[s][e], acc);
        acc += __shfl_xor_sync(0xffffffffu, acc, 1);
        acc += __shfl_xor_sync(0xffffffffu, acc, 2);
        sv[s] = acc;
    }
    if ((lane & 3) == 0) {
#pragma unroll
        for (int s = 0; s < 4; s++) {
            int rl = rloc0 + (s >> 1) * 16 + (s & 1) * 8;
            red[rl * 2 + wn] = sv[s];
        }
    }
    __syncthreads();
    if (tid < 128)
        g_q1[(size_t)(bt0 + tid) * N_AG + ag] = red[tid * 2] + red[tid * 2 + 1] + bv2[0];
}

// ---------------------------------------------------------------------------
// K3: per-row epilogue (unchanged)
// ---------------------------------------------------------------------------
__global__ void final_kernel(const float* __restrict__ qs,
                             const float* __restrict__ Wv2,
                             const float* __restrict__ bv2,
                             float* __restrict__ out) {
    __shared__ float absY[2048];
    __shared__ float qs2[32];
    __shared__ float red[4];

    const int b = blockIdx.x;
    const int e = threadIdx.x;
    const int lane = e & 31, warp = e >> 5;
    const float* Yr = g_Y + (size_t)b * NP;

    float h = 0.f;
#pragma unroll
    for (int a = 0; a < 32; a++) {
        float v = fabsf(Yr[a * 64 + e]);
        absY[a * 64 + e] = v;
        h = fmaf(qs[(size_t)b * N_AG + a], v, h);
    }
    float wf = fabsf(Yr[2048 + e]);
    float b1 = Yr[2112 + e];
    float rv = fmaxf(Yr[2176 + e], 0.f) * Wv2[e];

    float t = h + b1;
    float hid = t > 0.f ? t : expm1f(t);
    float s = hid * wf;
    float sv = rv;
#pragma unroll
    for (int off = 16; off >= 1; off >>= 1) {
        s  += __shfl_xor_sync(0xffffffffu, s, off);
        sv += __shfl_xor_sync(0xffffffffu, sv, off);
    }
    if (lane == 0) { red[warp] = s; red[2 + warp] = sv; }
    __syncthreads();

    float vtot  = red[2] + red[3] + bv2[0];
    float q_tot = red[0] + red[1] + vtot;

    if (e < 32) {
        float d = fabsf(q_tot - g_q1[(size_t)b * N_AG + e]);
        float d2 = d * d;
#pragma unroll
        for (int off = 16; off >= 1; off >>= 1)
            d2 += __shfl_xor_sync(0xffffffffu, d2, off);
        float nrm = fmaxf(sqrtf(d2), 1e-12f);
        qs2[e] = qs[(size_t)b * N_AG + e] * (d / nrm);
    }
    __syncthreads();

    float h2 = 0.f;
#pragma unroll
    for (int a = 0; a < 32; a++)
        h2 = fmaf(qs2[a], absY[a * 64 + e], h2);
    float t2 = h2 + b1;
    float hid2 = t2 > 0.f ? t2 : expm1f(t2);
    float s2 = hid2 * wf;
#pragma unroll
    for (int off = 16; off >= 1; off >>= 1)
        s2 += __shfl_xor_sync(0xffffffffu, s2, off);
    if (lane == 0) red[warp] = s2;
    __syncthreads();
    if (e == 0) out[b] = red[0] + red[1] + vtot;
}

// ---------------------------------------------------------------------------
extern "C" void kernel_launch(void* const* d_in, const int* in_sizes, int n_in,
                              void* d_out, int out_size) {
    const float* agent_qs = (const float*)d_in[0];
    const float* states   = (const float*)d_in[1];
    const float* Ww1 = (const float*)d_in[2];
    const float* bw1 = (const float*)d_in[3];
    const float* Wwf = (const float*)d_in[4];
    const float* bwf = (const float*)d_in[5];
    const float* Wb1 = (const float*)d_in[6];
    const float* bb1 = (const float*)d_in[7];
    const float* Wv1 = (const float*)d_in[8];
    const float* bv1 = (const float*)d_in[9];
    const float* Wv2 = (const float*)d_in[10];
    const float* bv2 = (const float*)d_in[11];
    float* out = (float*)d_out;

    static bool attr_done = false;
    if (!attr_done) {
        cudaFuncSetAttribute(gemm_ka, cudaFuncAttributeMaxDynamicSharedMemorySize, K1_SMEM);
        cudaFuncSetAttribute(corr_mma, cudaFuncAttributeMaxDynamicSharedMemorySize, K2_SMEM);
        attr_done = true;
    }

    pack_kernel<<<1024, 256>>>(states, Ww1, bw1, Wwf, bwf, Wb1, bb1, Wv1, bv1);
    gemm_ka<<<dim3(NP / 128, B_TOT / 128), 256, K1_SMEM>>>();
    corr_mma<<<dim3(B_TOT / 128, N_AG), 256, K2_SMEM>>>(agent_qs, Wv2, bv2);
    final_kernel<<<B_TOT, 64>>>(agent_qs, Wv2, bv2, out);
}

// round 7
// speedup vs baseline: 4.3968x; 1.1093x over previous
#include <cuda_runtime.h>
#include <cuda_fp16.h>
#include <math.h>
#include <stdint.h>

#define B_TOT 2048   // 64 * 32 rows
#define S_DIM 2048
#define N_AG  32
#define EMB   64
#define NP    2304   // padded concatenated output cols (2240 -> 18*128)
#define KSCALE 32.0f
#define KINV   0.03125f

// Scratch (device globals: no allocation allowed in kernel_launch)
__device__ __half g_Wh[S_DIM * NP];    // Wcat fp16 hi  [K][N]
__device__ __half g_Ws[S_DIM * NP];    // Wcat fp16 (h + 32*l)
__device__ __half g_Sh[B_TOT * S_DIM]; // st fp16 hi
__device__ __half g_Ss[B_TOT * S_DIM]; // st fp16 (h + 32*l)
__device__ float g_bcat[NP];
__device__ float g_Y[B_TOT * NP];      // st @ Wcat + bcat (fp32)
__device__ float g_q1[B_TOT * N_AG];   // masked-mix outputs

// ---------------------------------------------------------------------------
// helpers
// ---------------------------------------------------------------------------
__device__ __forceinline__ void ldsm_x4(uint32_t* r, const void* p) {
    uint32_t a = (uint32_t)__cvta_generic_to_shared(p);
    asm volatile("ldmatrix.sync.aligned.m8n8.x4.shared.b16 {%0,%1,%2,%3}, [%4];"
                 : "=r"(r[0]), "=r"(r[1]), "=r"(r[2]), "=r"(r[3]) : "r"(a));
}
__device__ __forceinline__ void ldsm_x4t(uint32_t* r, const void* p) {
    uint32_t a = (uint32_t)__cvta_generic_to_shared(p);
    asm volatile("ldmatrix.sync.aligned.m8n8.x4.trans.shared.b16 {%0,%1,%2,%3}, [%4];"
                 : "=r"(r[0]), "=r"(r[1]), "=r"(r[2]), "=r"(r[3]) : "r"(a));
}
__device__ __forceinline__ void mma_fp16(float* d, const uint32_t* a, const uint32_t* b) {
    asm volatile(
        "mma.sync.aligned.m16n8k16.row.col.f32.f16.f16.f32 "
        "{%0,%1,%2,%3},{%4,%5,%6,%7},{%8,%9},{%0,%1,%2,%3};"
        : "+f"(d[0]), "+f"(d[1]), "+f"(d[2]), "+f"(d[3])
        : "r"(a[0]), "r"(a[1]), "r"(a[2]), "r"(a[3]), "r"(b[0]), "r"(b[1]));
}
__device__ __forceinline__ void cp16(uint32_t dst, const void* src) {
    asm volatile("cp.async.cg.shared.global [%0], [%1], 16;" :: "r"(dst), "l"(src));
}
#define CP_COMMIT()  asm volatile("cp.async.commit_group;" ::: "memory")
#define CP_WAIT(n)   asm volatile("cp.async.wait_group %0;" :: "n"(n) : "memory")

__device__ __forceinline__ void splitk(float x, __half& h, __half& s) {
    __half hh = __float2half(x);
    float hf = __half2float(hh);
    h = hh;
    s = __float2half(hf + KSCALE * (x - hf));
}

// ---------------------------------------------------------------------------
// Pack: concat weights, fp16 Karatsuba splits for W and st, bias.
// ---------------------------------------------------------------------------
__global__ void pack_kernel(const float* __restrict__ st,
                            const float* __restrict__ Ww1, const float* __restrict__ bw1,
                            const float* __restrict__ Wwf, const float* __restrict__ bwf,
                            const float* __restrict__ Wb1, const float* __restrict__ bb1,
                            const float* __restrict__ Wv1, const float* __restrict__ bv1) {
    int idx = blockIdx.x * blockDim.x + threadIdx.x;
    int stride = gridDim.x * blockDim.x;
    if (idx < NP) {
        int n = idx;
        float bv;
        if (n < 2048)      bv = bw1[n];
        else if (n < 2112) bv = bwf[n - 2048];
        else if (n < 2176) bv = bb1[n - 2112];
        else if (n < 2240) bv = bv1[n - 2176];
        else               bv = 0.f;
        g_bcat[n] = bv;
    }
    for (int i = idx; i < S_DIM * NP; i += stride) {
        int k = i / NP, n = i - k * NP;
        float v;
        if (n < 2048)      v = Ww1[k * 2048 + n];
        else if (n < 2112) v = Wwf[k * 64 + (n - 2048)];
        else if (n < 2176) v = Wb1[k * 64 + (n - 2112)];
        else if (n < 2240) v = Wv1[k * 64 + (n - 2176)];
        else               v = 0.f;
        splitk(v, g_Wh[i], g_Ws[i]);
    }
    for (int i = idx; i < B_TOT * S_DIM; i += stride)
        splitk(st[i], g_Sh[i], g_Ss[i]);
}

// ---------------------------------------------------------------------------
// K1: Y = st @ Wcat + bcat via fp16 Karatsuba (2 MMAs per step):
//   D1 = h.h', D2 = S.S',  Y = D1 + (D2 - D1)/32.
// Block 128x128, 8 warps (4m x 2n), K-chunk 64, cp.async double buffer.
// ---------------------------------------------------------------------------
#define K1_OFF_AH 0
#define K1_OFF_AS 18432
#define K1_OFF_BH 36864
#define K1_OFF_BS 54272
#define K1_BUF    71680
#define K1_SMEM   (2 * K1_BUF)

__global__ __launch_bounds__(256, 1) void gemm_ka() {
    extern __shared__ char smem[];
    const uint32_t sbase = (uint32_t)__cvta_generic_to_shared(smem);

    const int bn = blockIdx.x * 128;
    const int bm = blockIdx.y * 128;
    const int tid = threadIdx.x;
    const int lane = tid & 31;
    const int warp = tid >> 5;
    const int wm = warp & 3;
    const int wn = warp >> 2;

    const int ra  = tid >> 3,  ca = tid & 7;
    const int rb  = tid >> 4,  cb = tid & 15;

    auto issue = [&](int c, int bufi) {
        const int k0 = c * 64;
        const uint32_t bb = sbase + bufi * K1_BUF;
#pragma unroll
        for (int l = 0; l < 4; l++) {
            int r = ra + l * 32;
            uint32_t off = (uint32_t)r * 144 + ca * 16;
            cp16(bb + K1_OFF_AH + off, g_Sh + (size_t)(bm + r) * S_DIM + k0 + ca * 8);
            cp16(bb + K1_OFF_AS + off, g_Ss + (size_t)(bm + r) * S_DIM + k0 + ca * 8);
            int rr = rb + l * 16;
            uint32_t offb = (uint32_t)rr * 272 + cb * 16;
            cp16(bb + K1_OFF_BH + offb, g_Wh + (size_t)(k0 + rr) * NP + bn + cb * 8);
            cp16(bb + K1_OFF_BS + offb, g_Ws + (size_t)(k0 + rr) * NP + bn + cb * 8);
        }
    };

    float d1[2][8][4], d2[2][8][4];
#pragma unroll
    for (int i = 0; i < 2; i++)
#pragma unroll
        for (int j = 0; j < 8; j++)
#pragma unroll
            for (int c = 0; c < 4; c++) { d1[i][j][c] = 0.f; d2[i][j][c] = 0.f; }

    issue(0, 0);
    CP_COMMIT();

    for (int c = 0; c < 32; c++) {
        const int bufi = c & 1;
        char* base = smem + bufi * K1_BUF;
        __half* Ah = (__half*)(base + K1_OFF_AH);
        __half* As = (__half*)(base + K1_OFF_AS);
        __half* Bh = (__half*)(base + K1_OFF_BH);
        __half* Bs = (__half*)(base + K1_OFF_BS);

        if (c < 31) {
            issue(c + 1, bufi ^ 1);
            CP_COMMIT();
            CP_WAIT(1);
        } else {
            CP_WAIT(0);
        }
        __syncthreads();

#pragma unroll
        for (int ks = 0; ks < 4; ks++) {
            uint32_t ah[2][4], as[2][4];
#pragma unroll
            for (int mf = 0; mf < 2; mf++) {
                const int ro = (wm * 32 + mf * 16 + (lane & 15)) * 72 + ks * 16 + (lane >> 4) * 8;
                ldsm_x4(ah[mf], &Ah[ro]);
                ldsm_x4(as[mf], &As[ro]);
            }
            uint32_t bh[8][2], bs[8][2];
#pragma unroll
            for (int nq = 0; nq < 4; nq++) {
                const int bo = (ks * 16 + (lane & 15)) * 136 + wn * 64 + nq * 16 + (lane >> 4) * 8;
                uint32_t t[4];
                ldsm_x4t(t, &Bh[bo]);
                bh[nq * 2][0] = t[0]; bh[nq * 2][1] = t[1];
                bh[nq * 2 + 1][0] = t[2]; bh[nq * 2 + 1][1] = t[3];
                ldsm_x4t(t, &Bs[bo]);
                bs[nq * 2][0] = t[0]; bs[nq * 2][1] = t[1];
                bs[nq * 2 + 1][0] = t[2]; bs[nq * 2 + 1][1] = t[3];
            }
#pragma unroll
            for (int mf = 0; mf < 2; mf++)
#pragma unroll
                for (int nf = 0; nf < 8; nf++) {
                    mma_fp16(d1[mf][nf], ah[mf], bh[nf]);
                    mma_fp16(d2[mf][nf], as[mf], bs[nf]);
                }
        }
        __syncthreads();
    }

#pragma unroll
    for (int mf = 0; mf < 2; mf++) {
        int r0 = bm + wm * 32 + mf * 16 + (lane >> 2);
#pragma unroll
        for (int nf = 0; nf < 8; nf++) {
            int c = bn + wn * 64 + nf * 8 + (lane & 3) * 2;
            float2 bc = *(const float2*)&g_bcat[c];
            float2 o0, o1;
            o0.x = d1[mf][nf][0] + (d2[mf][nf][0] - d1[mf][nf][0]) * KINV + bc.x;
            o0.y = d1[mf][nf][1] + (d2[mf][nf][1] - d1[mf][nf][1]) * KINV + bc.y;
            o1.x = d1[mf][nf][2] + (d2[mf][nf][2] - d1[mf][nf][2]) * KINV + bc.x;
            o1.y = d1[mf][nf][3] + (d2[mf][nf][3] - d1[mf][nf][3]) * KINV + bc.y;
            *(float2*)(g_Y + (size_t)r0 * NP + c) = o0;
            *(float2*)(g_Y + (size_t)(r0 + 8) * NP + c) = o1;
        }
    }
}

// ---------------------------------------------------------------------------
// K2: fused rank-64 correction + masked mix, restructured:
//  - hot loop = w1 groups 0..31 only (single code path, no wfm storage)
//  - tail order: 33 (b1/elu), 34 (v1), 32 (w_final consumed into running sum)
//  - on-demand Y loads; __launch_bounds__(256,2) -> 2 CTAs/SM
// ---------------------------------------------------------------------------
#define K2_SMEM (18432 + 18432 + 16896 + 1024)
__global__ __launch_bounds__(256, 2) void corr_mma(const float* __restrict__ qs,
                                                   const float* __restrict__ Wv2,
                                                   const float* __restrict__ bv2) {
    extern __shared__ char smem[];
    __half* Sf  = (__half*)smem;                  // [128][72]
    __half* Wgf = (__half*)(smem + 18432);        // [2][64][72]
    float* qs_s = (float*)(smem + 36864);         // [128][33]
    float* red  = (float*)(smem + 53760);         // [128][2]

    const int bt0 = blockIdx.x * 128;
    const int ag  = blockIdx.y;
    const int tid = threadIdx.x;
    const int lane = tid & 31;
    const int warp = tid >> 5;
    const int wm = warp & 3;
    const int wn = warp >> 2;

#pragma unroll
    for (int l = 0; l < 4; l++) {
        int idx = l * 256 + tid;
        int r = idx >> 3, c8 = idx & 7;
        *(uint4*)&Sf[r * 72 + c8 * 8] =
            *(const uint4*)(g_Sh + (size_t)(bt0 + r) * S_DIM + ag * 64 + c8 * 8);
    }
#pragma unroll
    for (int l = 0; l < 16; l++) {
        int idx = l * 256 + tid;
        int r = idx >> 5, c = idx & 31;
        qs_s[r * 33 + c] = qs[(size_t)(bt0 + r) * N_AG + c];
    }

    uint4 wf_r[2];
    auto loadW = [&](int g) {
#pragma unroll
        for (int l = 0; l < 2; l++) {
            int idx = l * 256 + tid;
            int r = idx >> 3, c8 = idx & 7;
            wf_r[l] = *(const uint4*)(g_Wh + (size_t)(ag * 64 + r) * NP + g * 64 + c8 * 8);
        }
    };
    auto storeW = [&](int b) {
#pragma unroll
        for (int l = 0; l < 2; l++) {
            int idx = l * 256 + tid;
            int r = idx >> 3, c8 = idx & 7;
            *(uint4*)&Wgf[b * 4608 + r * 72 + c8 * 8] = wf_r[l];
        }
    };
    loadW(0);
    storeW(0);

    // correction MMA for one 64-col group from weight buffer WgfB
    auto computeC = [&](const __half* WgfB, float (&c)[2][4][4]) {
#pragma unroll
        for (int mf = 0; mf < 2; mf++)
#pragma unroll
            for (int nf = 0; nf < 4; nf++)
#pragma unroll
                for (int q = 0; q < 4; q++) c[mf][nf][q] = 0.f;
#pragma unroll
        for (int ks = 0; ks < 4; ks++) {
            uint32_t af[2][4];
#pragma unroll
            for (int mf = 0; mf < 2; mf++) {
                const int ro = (wm * 32 + mf * 16 + (lane & 15)) * 72 + ks * 16 + (lane >> 4) * 8;
                ldsm_x4(af[mf], &Sf[ro]);
            }
            uint32_t bf[4][2];
#pragma unroll
            for (int nq = 0; nq < 2; nq++) {
                const int bo = (ks * 16 + (lane & 15)) * 72 + wn * 32 + nq * 16 + (lane >> 4) * 8;
                uint32_t t[4];
                ldsm_x4t(t, &WgfB[bo]);
                bf[nq * 2][0] = t[0]; bf[nq * 2][1] = t[1];
                bf[nq * 2 + 1][0] = t[2]; bf[nq * 2 + 1][1] = t[3];
            }
#pragma unroll
            for (int mf = 0; mf < 2; mf++)
#pragma unroll
                for (int nf = 0; nf < 4; nf++)
                    mma_fp16(c[mf][nf], af[mf], bf[nf]);
        }
    };

    const int rloc0 = wm * 32 + (lane >> 2);
    const int yr0 = bt0 + wm * 32 + (lane >> 2);
    float h[4][8];
#pragma unroll
    for (int s = 0; s < 4; s++)
#pragma unroll
        for (int e = 0; e < 8; e++) h[s][e] = 0.f;
    float vp[4] = {0.f, 0.f, 0.f, 0.f};

    // ---- hot loop: w1 groups 0..31 ----
    for (int g = 0; g < 32; g++) {
        __syncthreads();
        loadW(g == 31 ? 33 : g + 1);

        float c[2][4][4];
        computeC(Wgf + (g & 1) * 4608, c);

        float qv[4];
#pragma unroll
        for (int s = 0; s < 4; s++) {
            int rl = rloc0 + (s >> 1) * 16 + (s & 1) * 8;
            qv[s] = qs_s[rl * 33 + g];
        }
#pragma unroll
        for (int mf = 0; mf < 2; mf++) {
            int r0 = yr0 + mf * 16;
#pragma unroll
            for (int nf = 0; nf < 4; nf++) {
                int col = g * 64 + wn * 32 + nf * 8 + (lane & 3) * 2;
                float2 y0 = *(const float2*)(g_Y + (size_t)r0 * NP + col);
                float2 y1 = *(const float2*)(g_Y + (size_t)(r0 + 8) * NP + col);
                int s0 = mf * 2, s1 = mf * 2 + 1;
                int e0 = nf * 2, e1 = nf * 2 + 1;
                h[s0][e0] = fmaf(qv[s0], fabsf(y0.x - c[mf][nf][0]), h[s0][e0]);
                h[s0][e1] = fmaf(qv[s0], fabsf(y0.y - c[mf][nf][1]), h[s0][e1]);
                h[s1][e0] = fmaf(qv[s1], fabsf(y1.x - c[mf][nf][2]), h[s1][e0]);
                h[s1][e1] = fmaf(qv[s1], fabsf(y1.y - c[mf][nf][3]), h[s1][e1]);
            }
        }
        storeW((g + 1) & 1);
    }

    // ---- tail group 33 (b1): hidden = elu(h + m), buffer 0 ----
    __syncthreads();
    loadW(34);
    {
        float c[2][4][4];
        computeC(Wgf + 0 * 4608, c);
#pragma unroll
        for (int mf = 0; mf < 2; mf++) {
            int r0 = yr0 + mf * 16;
#pragma unroll
            for (int nf = 0; nf < 4; nf++) {
                int col = 33 * 64 + wn * 32 + nf * 8 + (lane & 3) * 2;
                float2 y0 = *(const float2*)(g_Y + (size_t)r0 * NP + col);
                float2 y1 = *(const float2*)(g_Y + (size_t)(r0 + 8) * NP + col);
                int s0 = mf * 2, s1 = mf * 2 + 1;
                int e0 = nf * 2, e1 = nf * 2 + 1;
                float t;
                t = h[s0][e0] + (y0.x - c[mf][nf][0]); h[s0][e0] = t > 0.f ? t : expm1f(t);
                t = h[s0][e1] + (y0.y - c[mf][nf][1]); h[s0][e1] = t > 0.f ? t : expm1f(t);
                t = h[s1][e0] + (y1.x - c[mf][nf][2]); h[s1][e0] = t > 0.f ? t : expm1f(t);
                t = h[s1][e1] + (y1.y - c[mf][nf][3]); h[s1][e1] = t > 0.f ? t : expm1f(t);
            }
        }
    }
    storeW(1);

    // ---- tail group 34 (v1): vp += relu(m) * Wv2, buffer 1 ----
    __syncthreads();
    loadW(32);
    {
        float c[2][4][4];
        computeC(Wgf + 1 * 4608, c);
#pragma unroll
        for (int mf = 0; mf < 2; mf++) {
            int r0 = yr0 + mf * 16;
#pragma unroll
            for (int nf = 0; nf < 4; nf++) {
                int e = wn * 32 + nf * 8 + (lane & 3) * 2;
                int col = 34 * 64 + e;
                float2 y0 = *(const float2*)(g_Y + (size_t)r0 * NP + col);
                float2 y1 = *(const float2*)(g_Y + (size_t)(r0 + 8) * NP + col);
                float w0 = Wv2[e], w1 = Wv2[e + 1];
                int s0 = mf * 2, s1 = mf * 2 + 1;
                vp[s0] = fmaf(fmaxf(y0.x - c[mf][nf][0], 0.f), w0, vp[s0]);
                vp[s0] = fmaf(fmaxf(y0.y - c[mf][nf][1], 0.f), w1, vp[s0]);
                vp[s1] = fmaf(fmaxf(y1.x - c[mf][nf][2], 0.f), w0, vp[s1]);
                vp[s1] = fmaf(fmaxf(y1.y - c[mf][nf][3], 0.f), w1, vp[s1]);
            }
        }
    }
    storeW(0);

    // ---- tail group 32 (w_final): s = vp + sum_e hidden * |m|, buffer 0 ----
    __syncthreads();
    float sacc[4] = { vp[0], vp[1], vp[2], vp[3] };
    {
        float c[2][4][4];
        computeC(Wgf + 0 * 4608, c);
#pragma unroll
        for (int mf = 0; mf < 2; mf++) {
            int r0 = yr0 + mf * 16;
#pragma unroll
            for (int nf = 0; nf < 4; nf++) {
                int col = 32 * 64 + wn * 32 + nf * 8 + (lane & 3) * 2;
                float2 y0 = *(const float2*)(g_Y + (size_t)r0 * NP + col);
                float2 y1 = *(const float2*)(g_Y + (size_t)(r0 + 8) * NP + col);
                int s0 = mf * 2, s1 = mf * 2 + 1;
                int e0 = nf * 2, e1 = nf * 2 + 1;
                sacc[s0] = fmaf(h[s0][e0], fabsf(y0.x - c[mf][nf][0]), sacc[s0]);
                sacc[s0] = fmaf(h[s0][e1], fabsf(y0.y - c[mf][nf][1]), sacc[s0]);
                sacc[s1] = fmaf(h[s1][e0], fabsf(y1.x - c[mf][nf][2]), sacc[s1]);
                sacc[s1] = fmaf(h[s1][e1], fabsf(y1.y - c[mf][nf][3]), sacc[s1]);
            }
        }
    }

#pragma unroll
    for (int s = 0; s < 4; s++) {
        sacc[s] += __shfl_xor_sync(0xffffffffu, sacc[s], 1);
        sacc[s] += __shfl_xor_sync(0xffffffffu, sacc[s], 2);
    }
    if ((lane & 3) == 0) {
#pragma unroll
        for (int s = 0; s < 4; s++) {
            int rl = rloc0 + (s >> 1) * 16 + (s & 1) * 8;
            red[rl * 2 + wn] = sacc[s];
        }
    }
    __syncthreads();
    if (tid < 128)
        g_q1[(size_t)(bt0 + tid) * N_AG + ag] = red[tid * 2] + red[tid * 2 + 1] + bv2[0];
}

// ---------------------------------------------------------------------------
// K3: per-row epilogue (unchanged)
// ---------------------------------------------------------------------------
__global__ void final_kernel(const float* __restrict__ qs,
                             const float* __restrict__ Wv2,
                             const float* __restrict__ bv2,
                             float* __restrict__ out) {
    __shared__ float absY[2048];
    __shared__ float qs2[32];
    __shared__ float red[4];

    const int b = blockIdx.x;
    const int e = threadIdx.x;
    const int lane = e & 31, warp = e >> 5;
    const float* Yr = g_Y + (size_t)b * NP;

    float h = 0.f;
#pragma unroll
    for (int a = 0; a < 32; a++) {
        float v = fabsf(Yr[a * 64 + e]);
        absY[a * 64 + e] = v;
        h = fmaf(qs[(size_t)b * N_AG + a], v, h);
    }
    float wf = fabsf(Yr[2048 + e]);
    float b1 = Yr[2112 + e];
    float rv = fmaxf(Yr[2176 + e], 0.f) * Wv2[e];

    float t = h + b1;
    float hid = t > 0.f ? t : expm1f(t);
    float s = hid * wf;
    float sv = rv;
#pragma unroll
    for (int off = 16; off >= 1; off >>= 1) {
        s  += __shfl_xor_sync(0xffffffffu, s, off);
        sv += __shfl_xor_sync(0xffffffffu, sv, off);
    }
    if (lane == 0) { red[warp] = s; red[2 + warp] = sv; }
    __syncthreads();

    float vtot  = red[2] + red[3] + bv2[0];
    float q_tot = red[0] + red[1] + vtot;

    if (e < 32) {
        float d = fabsf(q_tot - g_q1[(size_t)b * N_AG + e]);
        float d2 = d * d;
#pragma unroll
        for (int off = 16; off >= 1; off >>= 1)
            d2 += __shfl_xor_sync(0xffffffffu, d2, off);
        float nrm = fmaxf(sqrtf(d2), 1e-12f);
        qs2[e] = qs[(size_t)b * N_AG + e] * (d / nrm);
    }
    __syncthreads();

    float h2 = 0.f;
#pragma unroll
    for (int a = 0; a < 32; a++)
        h2 = fmaf(qs2[a], absY[a * 64 + e], h2);
    float t2 = h2 + b1;
    float hid2 = t2 > 0.f ? t2 : expm1f(t2);
    float s2 = hid2 * wf;
#pragma unroll
    for (int off = 16; off >= 1; off >>= 1)
        s2 += __shfl_xor_sync(0xffffffffu, s2, off);
    if (lane == 0) red[warp] = s2;
    __syncthreads();
    if (e == 0) out[b] = red[0] + red[1] + vtot;
}

// ---------------------------------------------------------------------------
extern "C" void kernel_launch(void* const* d_in, const int* in_sizes, int n_in,
                              void* d_out, int out_size) {
    const float* agent_qs = (const float*)d_in[0];
    const float* states   = (const float*)d_in[1];
    const float* Ww1 = (const float*)d_in[2];
    const float* bw1 = (const float*)d_in[3];
    const float* Wwf = (const float*)d_in[4];
    const float* bwf = (const float*)d_in[5];
    const float* Wb1 = (const float*)d_in[6];
    const float* bb1 = (const float*)d_in[7];
    const float* Wv1 = (const float*)d_in[8];
    const float* bv1 = (const float*)d_in[9];
    const float* Wv2 = (const float*)d_in[10];
    const float* bv2 = (const float*)d_in[11];
    float* out = (float*)d_out;

    static bool attr_done = false;
    if (!attr_done) {
        cudaFuncSetAttribute(gemm_ka, cudaFuncAttributeMaxDynamicSharedMemorySize, K1_SMEM);
        cudaFuncSetAttribute(corr_mma, cudaFuncAttributeMaxDynamicSharedMemorySize, K2_SMEM);
        attr_done = true;
    }

    pack_kernel<<<1024, 256>>>(states, Ww1, bw1, Wwf, bwf, Wb1, bb1, Wv1, bv1);
    gemm_ka<<<dim3(NP / 128, B_TOT / 128), 256, K1_SMEM>>>();
    corr_mma<<<dim3(B_TOT / 128, N_AG), 256, K2_SMEM>>>(agent_qs, Wv2, bv2);
    final_kernel<<<B_TOT, 64>>>(agent_qs, Wv2, bv2, out);
}

// round 8
// speedup vs baseline: 4.4688x; 1.0164x over previous
#include <cuda_runtime.h>
#include <cuda_fp16.h>
#include <math.h>
#include <stdint.h>

#define B_TOT 2048   // 64 * 32 rows
#define S_DIM 2048
#define N_AG  32
#define EMB   64
#define NP    2304   // padded concatenated output cols (2240 -> 18*128)
#define KSCALE 32.0f
#define KINV   0.03125f

// Scratch (device globals: no allocation allowed in kernel_launch)
__device__ __half g_Wh[S_DIM * NP];    // Wcat fp16 hi  [K][N]
__device__ __half g_Ws[S_DIM * NP];    // Wcat fp16 (h + 32*l)
__device__ __half g_Sh[B_TOT * S_DIM]; // st fp16 hi
__device__ __half g_Ss[B_TOT * S_DIM]; // st fp16 (h + 32*l)
__device__ float g_bcat[NP];
__device__ float g_Y[B_TOT * NP];      // st @ Wcat + bcat (fp32)
__device__ float g_q1[B_TOT * N_AG];   // masked-mix outputs

// ---------------------------------------------------------------------------
// helpers
// ---------------------------------------------------------------------------
__device__ __forceinline__ void ldsm_x4(uint32_t* r, const void* p) {
    uint32_t a = (uint32_t)__cvta_generic_to_shared(p);
    asm volatile("ldmatrix.sync.aligned.m8n8.x4.shared.b16 {%0,%1,%2,%3}, [%4];"
                 : "=r"(r[0]), "=r"(r[1]), "=r"(r[2]), "=r"(r[3]) : "r"(a));
}
__device__ __forceinline__ void ldsm_x4t(uint32_t* r, const void* p) {
    uint32_t a = (uint32_t)__cvta_generic_to_shared(p);
    asm volatile("ldmatrix.sync.aligned.m8n8.x4.trans.shared.b16 {%0,%1,%2,%3}, [%4];"
                 : "=r"(r[0]), "=r"(r[1]), "=r"(r[2]), "=r"(r[3]) : "r"(a));
}
__device__ __forceinline__ void mma_fp16(float* d, const uint32_t* a, const uint32_t* b) {
    asm volatile(
        "mma.sync.aligned.m16n8k16.row.col.f32.f16.f16.f32 "
        "{%0,%1,%2,%3},{%4,%5,%6,%7},{%8,%9},{%0,%1,%2,%3};"
        : "+f"(d[0]), "+f"(d[1]), "+f"(d[2]), "+f"(d[3])
        : "r"(a[0]), "r"(a[1]), "r"(a[2]), "r"(a[3]), "r"(b[0]), "r"(b[1]));
}
// fp16 accumulator variant (2x rate); d = 2 b32 regs holding 4 halves
__device__ __forceinline__ void mma_fp16h(uint32_t* d, const uint32_t* a, const uint32_t* b) {
    asm volatile(
        "mma.sync.aligned.m16n8k16.row.col.f16.f16.f16.f16 "
        "{%0,%1},{%2,%3,%4,%5},{%6,%7},{%0,%1};"
        : "+r"(d[0]), "+r"(d[1])
        : "r"(a[0]), "r"(a[1]), "r"(a[2]), "r"(a[3]), "r"(b[0]), "r"(b[1]));
}
__device__ __forceinline__ void cp16(uint32_t dst, const void* src) {
    asm volatile("cp.async.cg.shared.global [%0], [%1], 16;" :: "r"(dst), "l"(src));
}
#define CP_COMMIT()  asm volatile("cp.async.commit_group;" ::: "memory")
#define CP_WAIT(n)   asm volatile("cp.async.wait_group %0;" :: "n"(n) : "memory")

__device__ __forceinline__ void splitk(float x, __half& h, __half& s) {
    __half hh = __float2half(x);
    float hf = __half2float(hh);
    h = hh;
    s = __float2half(hf + KSCALE * (x - hf));
}

// ---------------------------------------------------------------------------
// Pack: concat weights, fp16 Karatsuba splits for W and st, bias.
// ---------------------------------------------------------------------------
__global__ void pack_kernel(const float* __restrict__ st,
                            const float* __restrict__ Ww1, const float* __restrict__ bw1,
                            const float* __restrict__ Wwf, const float* __restrict__ bwf,
                            const float* __restrict__ Wb1, const float* __restrict__ bb1,
                            const float* __restrict__ Wv1, const float* __restrict__ bv1) {
    int idx = blockIdx.x * blockDim.x + threadIdx.x;
    int stride = gridDim.x * blockDim.x;
    if (idx < NP) {
        int n = idx;
        float bv;
        if (n < 2048)      bv = bw1[n];
        else if (n < 2112) bv = bwf[n - 2048];
        else if (n < 2176) bv = bb1[n - 2112];
        else if (n < 2240) bv = bv1[n - 2176];
        else               bv = 0.f;
        g_bcat[n] = bv;
    }
    for (int i = idx; i < S_DIM * NP; i += stride) {
        int k = i / NP, n = i - k * NP;
        float v;
        if (n < 2048)      v = Ww1[k * 2048 + n];
        else if (n < 2112) v = Wwf[k * 64 + (n - 2048)];
        else if (n < 2176) v = Wb1[k * 64 + (n - 2112)];
        else if (n < 2240) v = Wv1[k * 64 + (n - 2176)];
        else               v = 0.f;
        splitk(v, g_Wh[i], g_Ws[i]);
    }
    for (int i = idx; i < B_TOT * S_DIM; i += stride)
        splitk(st[i], g_Sh[i], g_Ss[i]);
}

// ---------------------------------------------------------------------------
// K1: Y = st @ Wcat + bcat via fp16 Karatsuba:
//   D1 = h.h' (fp32 accum), D2 = S.S' (fp16 accum, 2x rate),
//   Y = D1 + (D2 - D1)/32.
// Block 128x128, 8 warps (4m x 2n), K-chunk 64, cp.async double buffer.
// ---------------------------------------------------------------------------
#define K1_OFF_AH 0
#define K1_OFF_AS 18432
#define K1_OFF_BH 36864
#define K1_OFF_BS 54272
#define K1_BUF    71680
#define K1_SMEM   (2 * K1_BUF)

__global__ __launch_bounds__(256, 1) void gemm_ka() {
    extern __shared__ char smem[];
    const uint32_t sbase = (uint32_t)__cvta_generic_to_shared(smem);

    const int bn = blockIdx.x * 128;
    const int bm = blockIdx.y * 128;
    const int tid = threadIdx.x;
    const int lane = tid & 31;
    const int warp = tid >> 5;
    const int wm = warp & 3;
    const int wn = warp >> 2;

    const int ra  = tid >> 3,  ca = tid & 7;
    const int rb  = tid >> 4,  cb = tid & 15;

    auto issue = [&](int c, int bufi) {
        const int k0 = c * 64;
        const uint32_t bb = sbase + bufi * K1_BUF;
#pragma unroll
        for (int l = 0; l < 4; l++) {
            int r = ra + l * 32;
            uint32_t off = (uint32_t)r * 144 + ca * 16;
            cp16(bb + K1_OFF_AH + off, g_Sh + (size_t)(bm + r) * S_DIM + k0 + ca * 8);
            cp16(bb + K1_OFF_AS + off, g_Ss + (size_t)(bm + r) * S_DIM + k0 + ca * 8);
            int rr = rb + l * 16;
            uint32_t offb = (uint32_t)rr * 272 + cb * 16;
            cp16(bb + K1_OFF_BH + offb, g_Wh + (size_t)(k0 + rr) * NP + bn + cb * 8);
            cp16(bb + K1_OFF_BS + offb, g_Ws + (size_t)(k0 + rr) * NP + bn + cb * 8);
        }
    };

    float d1[2][8][4];
    uint32_t d2[2][8][2];
#pragma unroll
    for (int i = 0; i < 2; i++)
#pragma unroll
        for (int j = 0; j < 8; j++) {
#pragma unroll
            for (int c = 0; c < 4; c++) d1[i][j][c] = 0.f;
            d2[i][j][0] = 0u; d2[i][j][1] = 0u;
        }

    issue(0, 0);
    CP_COMMIT();

    for (int c = 0; c < 32; c++) {
        const int bufi = c & 1;
        char* base = smem + bufi * K1_BUF;
        __half* Ah = (__half*)(base + K1_OFF_AH);
        __half* As = (__half*)(base + K1_OFF_AS);
        __half* Bh = (__half*)(base + K1_OFF_BH);
        __half* Bs = (__half*)(base + K1_OFF_BS);

        if (c < 31) {
            issue(c + 1, bufi ^ 1);
            CP_COMMIT();
            CP_WAIT(1);
        } else {
            CP_WAIT(0);
        }
        __syncthreads();

#pragma unroll
        for (int ks = 0; ks < 4; ks++) {
            uint32_t ah[2][4], as[2][4];
#pragma unroll
            for (int mf = 0; mf < 2; mf++) {
                const int ro = (wm * 32 + mf * 16 + (lane & 15)) * 72 + ks * 16 + (lane >> 4) * 8;
                ldsm_x4(ah[mf], &Ah[ro]);
                ldsm_x4(as[mf], &As[ro]);
            }
            uint32_t bh[8][2], bs[8][2];
#pragma unroll
            for (int nq = 0; nq < 4; nq++) {
                const int bo = (ks * 16 + (lane & 15)) * 136 + wn * 64 + nq * 16 + (lane >> 4) * 8;
                uint32_t t[4];
                ldsm_x4t(t, &Bh[bo]);
                bh[nq * 2][0] = t[0]; bh[nq * 2][1] = t[1];
                bh[nq * 2 + 1][0] = t[2]; bh[nq * 2 + 1][1] = t[3];
                ldsm_x4t(t, &Bs[bo]);
                bs[nq * 2][0] = t[0]; bs[nq * 2][1] = t[1];
                bs[nq * 2 + 1][0] = t[2]; bs[nq * 2 + 1][1] = t[3];
            }
#pragma unroll
            for (int mf = 0; mf < 2; mf++)
#pragma unroll
                for (int nf = 0; nf < 8; nf++) {
                    mma_fp16(d1[mf][nf], ah[mf], bh[nf]);
                    mma_fp16h(d2[mf][nf], as[mf], bs[nf]);
                }
        }
        __syncthreads();
    }

    // epilogue: Y = d1 + (d2 - d1)/32 + bias
#pragma unroll
    for (int mf = 0; mf < 2; mf++) {
        int r0 = bm + wm * 32 + mf * 16 + (lane >> 2);
#pragma unroll
        for (int nf = 0; nf < 8; nf++) {
            int c = bn + wn * 64 + nf * 8 + (lane & 3) * 2;
            float2 bc = *(const float2*)&g_bcat[c];
            float2 f0 = __half22float2(*reinterpret_cast<__half2*>(&d2[mf][nf][0]));
            float2 f1 = __half22float2(*reinterpret_cast<__half2*>(&d2[mf][nf][1]));
            float2 o0, o1;
            o0.x = d1[mf][nf][0] + (f0.x - d1[mf][nf][0]) * KINV + bc.x;
            o0.y = d1[mf][nf][1] + (f0.y - d1[mf][nf][1]) * KINV + bc.y;
            o1.x = d1[mf][nf][2] + (f1.x - d1[mf][nf][2]) * KINV + bc.x;
            o1.y = d1[mf][nf][3] + (f1.y - d1[mf][nf][3]) * KINV + bc.y;
            *(float2*)(g_Y + (size_t)r0 * NP + c) = o0;
            *(float2*)(g_Y + (size_t)(r0 + 8) * NP + c) = o1;
        }
    }
}

// ---------------------------------------------------------------------------
// K2: fused rank-64 correction + masked mix; cp.async weight double buffer.
// Hot loop = w1 groups 0..31; tail order 33 (b1/elu), 34 (v1), 32 (w_final).
// __launch_bounds__(256,2) -> 2 CTAs/SM.
// ---------------------------------------------------------------------------
#define K2_OFF_W   18432
#define K2_WBUF    9216
#define K2_OFF_QS  36864
#define K2_OFF_RED 53760
#define K2_SMEM    (18432 + 18432 + 16896 + 1024)
__global__ __launch_bounds__(256, 2) void corr_mma(const float* __restrict__ qs,
                                                   const float* __restrict__ Wv2,
                                                   const float* __restrict__ bv2) {
    extern __shared__ char smem[];
    const uint32_t sbase = (uint32_t)__cvta_generic_to_shared(smem);
    __half* Sf  = (__half*)smem;                    // [128][72]
    __half* Wgf = (__half*)(smem + K2_OFF_W);       // [2][64][72]
    float* qs_s = (float*)(smem + K2_OFF_QS);       // [128][33]
    float* red  = (float*)(smem + K2_OFF_RED);      // [128][2]

    const int bt0 = blockIdx.x * 128;
    const int ag  = blockIdx.y;
    const int tid = threadIdx.x;
    const int lane = tid & 31;
    const int warp = tid >> 5;
    const int wm = warp & 3;
    const int wn = warp >> 2;

#pragma unroll
    for (int l = 0; l < 4; l++) {
        int idx = l * 256 + tid;
        int r = idx >> 3, c8 = idx & 7;
        *(uint4*)&Sf[r * 72 + c8 * 8] =
            *(const uint4*)(g_Sh + (size_t)(bt0 + r) * S_DIM + ag * 64 + c8 * 8);
    }
#pragma unroll
    for (int l = 0; l < 16; l++) {
        int idx = l * 256 + tid;
        int r = idx >> 5, c = idx & 31;
        qs_s[r * 33 + c] = qs[(size_t)(bt0 + r) * N_AG + c];
    }

    // cp.async prefetch of one 64x64 weight group into buffer b
    const int wr = tid >> 3, wc8 = tid & 7;
    auto issueW = [&](int g, int b) {
#pragma unroll
        for (int l = 0; l < 2; l++) {
            int r = wr + l * 32;
            cp16(sbase + K2_OFF_W + b * K2_WBUF + (uint32_t)r * 144 + wc8 * 16,
                 g_Wh + (size_t)(ag * 64 + r) * NP + g * 64 + wc8 * 8);
        }
    };

    auto computeC = [&](const __half* WgfB, float (&c)[2][4][4]) {
#pragma unroll
        for (int mf = 0; mf < 2; mf++)
#pragma unroll
            for (int nf = 0; nf < 4; nf++)
#pragma unroll
                for (int q = 0; q < 4; q++) c[mf][nf][q] = 0.f;
#pragma unroll
        for (int ks = 0; ks < 4; ks++) {
            uint32_t af[2][4];
#pragma unroll
            for (int mf = 0; mf < 2; mf++) {
                const int ro = (wm * 32 + mf * 16 + (lane & 15)) * 72 + ks * 16 + (lane >> 4) * 8;
                ldsm_x4(af[mf], &Sf[ro]);
            }
            uint32_t bf[4][2];
#pragma unroll
            for (int nq = 0; nq < 2; nq++) {
                const int bo = (ks * 16 + (lane & 15)) * 72 + wn * 32 + nq * 16 + (lane >> 4) * 8;
                uint32_t t[4];
                ldsm_x4t(t, &WgfB[bo]);
                bf[nq * 2][0] = t[0]; bf[nq * 2][1] = t[1];
                bf[nq * 2 + 1][0] = t[2]; bf[nq * 2 + 1][1] = t[3];
            }
#pragma unroll
            for (int mf = 0; mf < 2; mf++)
#pragma unroll
                for (int nf = 0; nf < 4; nf++)
                    mma_fp16(c[mf][nf], af[mf], bf[nf]);
        }
    };

    const int rloc0 = wm * 32 + (lane >> 2);
    const int yr0 = bt0 + wm * 32 + (lane >> 2);
    float h[4][8];
#pragma unroll
    for (int s = 0; s < 4; s++)
#pragma unroll
        for (int e = 0; e < 8; e++) h[s][e] = 0.f;
    float vp[4] = {0.f, 0.f, 0.f, 0.f};

    issueW(0, 0);
    CP_COMMIT();

    // ---- hot loop: w1 groups 0..31 ----
    for (int g = 0; g < 32; g++) {
        CP_WAIT(0);
        __syncthreads();
        issueW(g == 31 ? 33 : g + 1, (g + 1) & 1);
        CP_COMMIT();

        float c[2][4][4];
        computeC(Wgf + (g & 1) * 4608, c);

        float qv[4];
#pragma unroll
        for (int s = 0; s < 4; s++) {
            int rl = rloc0 + (s >> 1) * 16 + (s & 1) * 8;
            qv[s] = qs_s[rl * 33 + g];
        }
#pragma unroll
        for (int mf = 0; mf < 2; mf++) {
            int r0 = yr0 + mf * 16;
#pragma unroll
            for (int nf = 0; nf < 4; nf++) {
                int col = g * 64 + wn * 32 + nf * 8 + (lane & 3) * 2;
                float2 y0 = *(const float2*)(g_Y + (size_t)r0 * NP + col);
                float2 y1 = *(const float2*)(g_Y + (size_t)(r0 + 8) * NP + col);
                int s0 = mf * 2, s1 = mf * 2 + 1;
                int e0 = nf * 2, e1 = nf * 2 + 1;
                h[s0][e0] = fmaf(qv[s0], fabsf(y0.x - c[mf][nf][0]), h[s0][e0]);
                h[s0][e1] = fmaf(qv[s0], fabsf(y0.y - c[mf][nf][1]), h[s0][e1]);
                h[s1][e0] = fmaf(qv[s1], fabsf(y1.x - c[mf][nf][2]), h[s1][e0]);
                h[s1][e1] = fmaf(qv[s1], fabsf(y1.y - c[mf][nf][3]), h[s1][e1]);
            }
        }
    }

    // ---- tail group 33 (b1): hidden = elu(h + m), buffer 0 ----
    CP_WAIT(0);
    __syncthreads();
    issueW(34, 1);
    CP_COMMIT();
    {
        float c[2][4][4];
        computeC(Wgf + 0 * 4608, c);
#pragma unroll
        for (int mf = 0; mf < 2; mf++) {
            int r0 = yr0 + mf * 16;
#pragma unroll
            for (int nf = 0; nf < 4; nf++) {
                int col = 33 * 64 + wn * 32 + nf * 8 + (lane & 3) * 2;
                float2 y0 = *(const float2*)(g_Y + (size_t)r0 * NP + col);
                float2 y1 = *(const float2*)(g_Y + (size_t)(r0 + 8) * NP + col);
                int s0 = mf * 2, s1 = mf * 2 + 1;
                int e0 = nf * 2, e1 = nf * 2 + 1;
                float t;
                t = h[s0][e0] + (y0.x - c[mf][nf][0]); h[s0][e0] = t > 0.f ? t : expm1f(t);
                t = h[s0][e1] + (y0.y - c[mf][nf][1]); h[s0][e1] = t > 0.f ? t : expm1f(t);
                t = h[s1][e0] + (y1.x - c[mf][nf][2]); h[s1][e0] = t > 0.f ? t : expm1f(t);
                t = h[s1][e1] + (y1.y - c[mf][nf][3]); h[s1][e1] = t > 0.f ? t : expm1f(t);
            }
        }
    }

    // ---- tail group 34 (v1): vp += relu(m) * Wv2, buffer 1 ----
    CP_WAIT(0);
    __syncthreads();
    issueW(32, 0);
    CP_COMMIT();
    {
        float c[2][4][4];
        computeC(Wgf + 1 * 4608, c);
#pragma unroll
        for (int mf = 0; mf < 2; mf++) {
            int r0 = yr0 + mf * 16;
#pragma unroll
            for (int nf = 0; nf < 4; nf++) {
                int e = wn * 32 + nf * 8 + (lane & 3) * 2;
                int col = 34 * 64 + e;
                float2 y0 = *(const float2*)(g_Y + (size_t)r0 * NP + col);
                float2 y1 = *(const float2*)(g_Y + (size_t)(r0 + 8) * NP + col);
                float w0 = Wv2[e], w1 = Wv2[e + 1];
                int s0 = mf * 2, s1 = mf * 2 + 1;
                vp[s0] = fmaf(fmaxf(y0.x - c[mf][nf][0], 0.f), w0, vp[s0]);
                vp[s0] = fmaf(fmaxf(y0.y - c[mf][nf][1], 0.f), w1, vp[s0]);
                vp[s1] = fmaf(fmaxf(y1.x - c[mf][nf][2], 0.f), w0, vp[s1]);
                vp[s1] = fmaf(fmaxf(y1.y - c[mf][nf][3], 0.f), w1, vp[s1]);
            }
        }
    }

    // ---- tail group 32 (w_final): s = vp + sum_e hidden * |m|, buffer 0 ----
    CP_WAIT(0);
    __syncthreads();
    float sacc[4] = { vp[0], vp[1], vp[2], vp[3] };
    {
        float c[2][4][4];
        computeC(Wgf + 0 * 4608, c);
#pragma unroll
        for (int mf = 0; mf < 2; mf++) {
            int r0 = yr0 + mf * 16;
#pragma unroll
            for (int nf = 0; nf < 4; nf++) {
                int col = 32 * 64 + wn * 32 + nf * 8 + (lane & 3) * 2;
                float2 y0 = *(const float2*)(g_Y + (size_t)r0 * NP + col);
                float2 y1 = *(const float2*)(g_Y + (size_t)(r0 + 8) * NP + col);
                int s0 = mf * 2, s1 = mf * 2 + 1;
                int e0 = nf * 2, e1 = nf * 2 + 1;
                sacc[s0] = fmaf(h[s0][e0], fabsf(y0.x - c[mf][nf][0]), sacc[s0]);
                sacc[s0] = fmaf(h[s0][e1], fabsf(y0.y - c[mf][nf][1]), sacc[s0]);
                sacc[s1] = fmaf(h[s1][e0], fabsf(y1.x - c[mf][nf][2]), sacc[s1]);
                sacc[s1] = fmaf(h[s1][e1], fabsf(y1.y - c[mf][nf][3]), sacc[s1]);
            }
        }
    }

#pragma unroll
    for (int s = 0; s < 4; s++) {
        sacc[s] += __shfl_xor_sync(0xffffffffu, sacc[s], 1);
        sacc[s] += __shfl_xor_sync(0xffffffffu, sacc[s], 2);
    }
    if ((lane & 3) == 0) {
#pragma unroll
        for (int s = 0; s < 4; s++) {
            int rl = rloc0 + (s >> 1) * 16 + (s & 1) * 8;
            red[rl * 2 + wn] = sacc[s];
        }
    }
    __syncthreads();
    if (tid < 128)
        g_q1[(size_t)(bt0 + tid) * N_AG + ag] = red[tid * 2] + red[tid * 2 + 1] + bv2[0];
}

// ---------------------------------------------------------------------------
// K3: per-row epilogue (unchanged)
// ---------------------------------------------------------------------------
__global__ void final_kernel(const float* __restrict__ qs,
                             const float* __restrict__ Wv2,
                             const float* __restrict__ bv2,
                             float* __restrict__ out) {
    __shared__ float absY[2048];
    __shared__ float qs2[32];
    __shared__ float red[4];

    const int b = blockIdx.x;
    const int e = threadIdx.x;
    const int lane = e & 31, warp = e >> 5;
    const float* Yr = g_Y + (size_t)b * NP;

    float h = 0.f;
#pragma unroll
    for (int a = 0; a < 32; a++) {
        float v = fabsf(Yr[a * 64 + e]);
        absY[a * 64 + e] = v;
        h = fmaf(qs[(size_t)b * N_AG + a], v, h);
    }
    float wf = fabsf(Yr[2048 + e]);
    float b1 = Yr[2112 + e];
    float rv = fmaxf(Yr[2176 + e], 0.f) * Wv2[e];

    float t = h + b1;
    float hid = t > 0.f ? t : expm1f(t);
    float s = hid * wf;
    float sv = rv;
#pragma unroll
    for (int off = 16; off >= 1; off >>= 1) {
        s  += __shfl_xor_sync(0xffffffffu, s, off);
        sv += __shfl_xor_sync(0xffffffffu, sv, off);
    }
    if (lane == 0) { red[warp] = s; red[2 + warp] = sv; }
    __syncthreads();

    float vtot  = red[2] + red[3] + bv2[0];
    float q_tot = red[0] + red[1] + vtot;

    if (e < 32) {
        float d = fabsf(q_tot - g_q1[(size_t)b * N_AG + e]);
        float d2 = d * d;
#pragma unroll
        for (int off = 16; off >= 1; off >>= 1)
            d2 += __shfl_xor_sync(0xffffffffu, d2, off);
        float nrm = fmaxf(sqrtf(d2), 1e-12f);
        qs2[e] = qs[(size_t)b * N_AG + e] * (d / nrm);
    }
    __syncthreads();

    float h2 = 0.f;
#pragma unroll
    for (int a = 0; a < 32; a++)
        h2 = fmaf(qs2[a], absY[a * 64 + e], h2);
    float t2 = h2 + b1;
    float hid2 = t2 > 0.f ? t2 : expm1f(t2);
    float s2 = hid2 * wf;
#pragma unroll
    for (int off = 16; off >= 1; off >>= 1)
        s2 += __shfl_xor_sync(0xffffffffu, s2, off);
    if (lane == 0) red[warp] = s2;
    __syncthreads();
    if (e == 0) out[b] = red[0] + red[1] + vtot;
}

// ---------------------------------------------------------------------------
extern "C" void kernel_launch(void* const* d_in, const int* in_sizes, int n_in,
                              void* d_out, int out_size) {
    const float* agent_qs = (const float*)d_in[0];
    const float* states   = (const float*)d_in[1];
    const float* Ww1 = (const float*)d_in[2];
    const float* bw1 = (const float*)d_in[3];
    const float* Wwf = (const float*)d_in[4];
    const float* bwf = (const float*)d_in[5];
    const float* Wb1 = (const float*)d_in[6];
    const float* bb1 = (const float*)d_in[7];
    const float* Wv1 = (const float*)d_in[8];
    const float* bv1 = (const float*)d_in[9];
    const float* Wv2 = (const float*)d_in[10];
    const float* bv2 = (const float*)d_in[11];
    float* out = (float*)d_out;

    static bool attr_done = false;
    if (!attr_done) {
        cudaFuncSetAttribute(gemm_ka, cudaFuncAttributeMaxDynamicSharedMemorySize, K1_SMEM);
        cudaFuncSetAttribute(corr_mma, cudaFuncAttributeMaxDynamicSharedMemorySize, K2_SMEM);
        attr_done = true;
    }

    pack_kernel<<<1024, 256>>>(states, Ww1, bw1, Wwf, bwf, Wb1, bb1, Wv1, bv1);
    gemm_ka<<<dim3(NP / 128, B_TOT / 128), 256, K1_SMEM>>>();
    corr_mma<<<dim3(B_TOT / 128, N_AG), 256, K2_SMEM>>>(agent_qs, Wv2, bv2);
    final_kernel<<<B_TOT, 64>>>(agent_qs, Wv2, bv2, out);
}

// round 9
// speedup vs baseline: 4.4789x; 1.0023x over previous
#include <cuda_runtime.h>
#include <cuda_fp16.h>
#include <math.h>
#include <stdint.h>

#define B_TOT 2048   // 64 * 32 rows
#define S_DIM 2048
#define N_AG  32
#define EMB   64
#define NP    2304   // padded concatenated output cols (2240 -> 18*128)
#define KSCALE 32.0f
#define KINV   0.03125f

// Scratch (device globals: no allocation allowed in kernel_launch)
__device__ __half g_Wh[S_DIM * NP];    // Wcat fp16 hi  [K][N]
__device__ __half g_Ws[S_DIM * NP];    // Wcat fp16 (h + 32*l)
__device__ __half g_Sh[B_TOT * S_DIM]; // st fp16 hi
__device__ __half g_Ss[B_TOT * S_DIM]; // st fp16 (h + 32*l)
__device__ float g_bcat[NP];
__device__ float g_Y[B_TOT * NP];      // st @ Wcat + bcat (fp32)
__device__ float g_q1[B_TOT * N_AG];   // masked-mix outputs

// ---------------------------------------------------------------------------
// helpers
// ---------------------------------------------------------------------------
__device__ __forceinline__ void ldsm_x4(uint32_t* r, const void* p) {
    uint32_t a = (uint32_t)__cvta_generic_to_shared(p);
    asm volatile("ldmatrix.sync.aligned.m8n8.x4.shared.b16 {%0,%1,%2,%3}, [%4];"
                 : "=r"(r[0]), "=r"(r[1]), "=r"(r[2]), "=r"(r[3]) : "r"(a));
}
__device__ __forceinline__ void ldsm_x4t(uint32_t* r, const void* p) {
    uint32_t a = (uint32_t)__cvta_generic_to_shared(p);
    asm volatile("ldmatrix.sync.aligned.m8n8.x4.trans.shared.b16 {%0,%1,%2,%3}, [%4];"
                 : "=r"(r[0]), "=r"(r[1]), "=r"(r[2]), "=r"(r[3]) : "r"(a));
}
__device__ __forceinline__ void mma_fp16(float* d, const uint32_t* a, const uint32_t* b) {
    asm volatile(
        "mma.sync.aligned.m16n8k16.row.col.f32.f16.f16.f32 "
        "{%0,%1,%2,%3},{%4,%5,%6,%7},{%8,%9},{%0,%1,%2,%3};"
        : "+f"(d[0]), "+f"(d[1]), "+f"(d[2]), "+f"(d[3])
        : "r"(a[0]), "r"(a[1]), "r"(a[2]), "r"(a[3]), "r"(b[0]), "r"(b[1]));
}
// fp16 accumulator variant (register-lean); d = 2 b32 regs holding 4 halves
__device__ __forceinline__ void mma_fp16h(uint32_t* d, const uint32_t* a, const uint32_t* b) {
    asm volatile(
        "mma.sync.aligned.m16n8k16.row.col.f16.f16.f16.f16 "
        "{%0,%1},{%2,%3,%4,%5},{%6,%7},{%0,%1};"
        : "+r"(d[0]), "+r"(d[1])
        : "r"(a[0]), "r"(a[1]), "r"(a[2]), "r"(a[3]), "r"(b[0]), "r"(b[1]));
}
__device__ __forceinline__ void cp16(uint32_t dst, const void* src) {
    asm volatile("cp.async.cg.shared.global [%0], [%1], 16;" :: "r"(dst), "l"(src));
}
#define CP_COMMIT()  asm volatile("cp.async.commit_group;" ::: "memory")
#define CP_WAIT(n)   asm volatile("cp.async.wait_group %0;" :: "n"(n) : "memory")

__device__ __forceinline__ void splitk(float x, __half& h, __half& s) {
    __half hh = __float2half(x);
    float hf = __half2float(hh);
    h = hh;
    s = __float2half(hf + KSCALE * (x - hf));
}

// ---------------------------------------------------------------------------
// Pack (vectorized): concat weights, fp16 Karatsuba splits, bias.
// float4 reads, half2-pair writes, div-by-constant indexing only.
// ---------------------------------------------------------------------------
__global__ void pack_kernel(const float* __restrict__ st,
                            const float* __restrict__ Ww1, const float* __restrict__ bw1,
                            const float* __restrict__ Wwf, const float* __restrict__ bwf,
                            const float* __restrict__ Wb1, const float* __restrict__ bb1,
                            const float* __restrict__ Wv1, const float* __restrict__ bv1) {
    const int idx = blockIdx.x * blockDim.x + threadIdx.x;
    const int stride = gridDim.x * blockDim.x;

    if (idx < NP) {
        int n = idx;
        float bv;
        if (n < 2048)      bv = bw1[n];
        else if (n < 2112) bv = bwf[n - 2048];
        else if (n < 2176) bv = bb1[n - 2112];
        else if (n < 2240) bv = bv1[n - 2176];
        else               bv = 0.f;
        g_bcat[n] = bv;
    }

    // W region: S_DIM x NP, processed as float4 quads (576 per row)
    const int WQ = S_DIM * (NP / 4);
    for (int i = idx; i < WQ; i += stride) {
        int k = i / 576;
        int n = (i - k * 576) * 4;
        float4 v;
        if (n < 2048)      v = *(const float4*)(Ww1 + (size_t)k * 2048 + n);
        else if (n < 2112) v = *(const float4*)(Wwf + (size_t)k * 64 + (n - 2048));
        else if (n < 2176) v = *(const float4*)(Wb1 + (size_t)k * 64 + (n - 2112));
        else if (n < 2240) v = *(const float4*)(Wv1 + (size_t)k * 64 + (n - 2176));
        else               v = make_float4(0.f, 0.f, 0.f, 0.f);
        __half h0, h1, h2, h3, s0, s1, s2, s3;
        splitk(v.x, h0, s0); splitk(v.y, h1, s1);
        splitk(v.z, h2, s2); splitk(v.w, h3, s3);
        __half2* ph = (__half2*)(g_Wh + (size_t)i * 4);
        ph[0] = __halves2half2(h0, h1); ph[1] = __halves2half2(h2, h3);
        __half2* ps = (__half2*)(g_Ws + (size_t)i * 4);
        ps[0] = __halves2half2(s0, s1); ps[1] = __halves2half2(s2, s3);
    }

    // st region: B_TOT x S_DIM as float4 quads (power-of-2 indexing)
    const int SQ = B_TOT * (S_DIM / 4);
    for (int i = idx; i < SQ; i += stride) {
        float4 v = *(const float4*)(st + (size_t)i * 4);
        __half h0, h1, h2, h3, s0, s1, s2, s3;
        splitk(v.x, h0, s0); splitk(v.y, h1, s1);
        splitk(v.z, h2, s2); splitk(v.w, h3, s3);
        __half2* ph = (__half2*)(g_Sh + (size_t)i * 4);
        ph[0] = __halves2half2(h0, h1); ph[1] = __halves2half2(h2, h3);
        __half2* ps = (__half2*)(g_Ss + (size_t)i * 4);
        ps[0] = __halves2half2(s0, s1); ps[1] = __halves2half2(s2, s3);
    }
}

// ---------------------------------------------------------------------------
// K1: Y = st @ Wcat + bcat via fp16 Karatsuba:
//   D1 = h.h' (fp32 accum), D2 = S.S' (fp16 accum), Y = D1 + (D2 - D1)/32.
// Block 128x128, 8 warps (4m x 2n), K-chunk 64, cp.async double buffer.
// ---------------------------------------------------------------------------
#define K1_OFF_AH 0
#define K1_OFF_AS 18432
#define K1_OFF_BH 36864
#define K1_OFF_BS 54272
#define K1_BUF    71680
#define K1_SMEM   (2 * K1_BUF)

__global__ __launch_bounds__(256, 1) void gemm_ka() {
    extern __shared__ char smem[];
    const uint32_t sbase = (uint32_t)__cvta_generic_to_shared(smem);

    const int bn = blockIdx.x * 128;
    const int bm = blockIdx.y * 128;
    const int tid = threadIdx.x;
    const int lane = tid & 31;
    const int warp = tid >> 5;
    const int wm = warp & 3;
    const int wn = warp >> 2;

    const int ra  = tid >> 3,  ca = tid & 7;
    const int rb  = tid >> 4,  cb = tid & 15;

    auto issue = [&](int c, int bufi) {
        const int k0 = c * 64;
        const uint32_t bb = sbase + bufi * K1_BUF;
#pragma unroll
        for (int l = 0; l < 4; l++) {
            int r = ra + l * 32;
            uint32_t off = (uint32_t)r * 144 + ca * 16;
            cp16(bb + K1_OFF_AH + off, g_Sh + (size_t)(bm + r) * S_DIM + k0 + ca * 8);
            cp16(bb + K1_OFF_AS + off, g_Ss + (size_t)(bm + r) * S_DIM + k0 + ca * 8);
            int rr = rb + l * 16;
            uint32_t offb = (uint32_t)rr * 272 + cb * 16;
            cp16(bb + K1_OFF_BH + offb, g_Wh + (size_t)(k0 + rr) * NP + bn + cb * 8);
            cp16(bb + K1_OFF_BS + offb, g_Ws + (size_t)(k0 + rr) * NP + bn + cb * 8);
        }
    };

    float d1[2][8][4];
    uint32_t d2[2][8][2];
#pragma unroll
    for (int i = 0; i < 2; i++)
#pragma unroll
        for (int j = 0; j < 8; j++) {
#pragma unroll
            for (int c = 0; c < 4; c++) d1[i][j][c] = 0.f;
            d2[i][j][0] = 0u; d2[i][j][1] = 0u;
        }

    issue(0, 0);
    CP_COMMIT();

    for (int c = 0; c < 32; c++) {
        const int bufi = c & 1;
        char* base = smem + bufi * K1_BUF;
        __half* Ah = (__half*)(base + K1_OFF_AH);
        __half* As = (__half*)(base + K1_OFF_AS);
        __half* Bh = (__half*)(base + K1_OFF_BH);
        __half* Bs = (__half*)(base + K1_OFF_BS);

        if (c < 31) {
            issue(c + 1, bufi ^ 1);
            CP_COMMIT();
            CP_WAIT(1);
        } else {
            CP_WAIT(0);
        }
        __syncthreads();

#pragma unroll
        for (int ks = 0; ks < 4; ks++) {
            uint32_t ah[2][4], as[2][4];
#pragma unroll
            for (int mf = 0; mf < 2; mf++) {
                const int ro = (wm * 32 + mf * 16 + (lane & 15)) * 72 + ks * 16 + (lane >> 4) * 8;
                ldsm_x4(ah[mf], &Ah[ro]);
                ldsm_x4(as[mf], &As[ro]);
            }
            uint32_t bh[8][2], bs[8][2];
#pragma unroll
            for (int nq = 0; nq < 4; nq++) {
                const int bo = (ks * 16 + (lane & 15)) * 136 + wn * 64 + nq * 16 + (lane >> 4) * 8;
                uint32_t t[4];
                ldsm_x4t(t, &Bh[bo]);
                bh[nq * 2][0] = t[0]; bh[nq * 2][1] = t[1];
                bh[nq * 2 + 1][0] = t[2]; bh[nq * 2 + 1][1] = t[3];
                ldsm_x4t(t, &Bs[bo]);
                bs[nq * 2][0] = t[0]; bs[nq * 2][1] = t[1];
                bs[nq * 2 + 1][0] = t[2]; bs[nq * 2 + 1][1] = t[3];
            }
#pragma unroll
            for (int mf = 0; mf < 2; mf++)
#pragma unroll
                for (int nf = 0; nf < 8; nf++) {
                    mma_fp16(d1[mf][nf], ah[mf], bh[nf]);
                    mma_fp16h(d2[mf][nf], as[mf], bs[nf]);
                }
        }
        __syncthreads();
    }

    // epilogue: Y = d1 + (d2 - d1)/32 + bias
#pragma unroll
    for (int mf = 0; mf < 2; mf++) {
        int r0 = bm + wm * 32 + mf * 16 + (lane >> 2);
#pragma unroll
        for (int nf = 0; nf < 8; nf++) {
            int c = bn + wn * 64 + nf * 8 + (lane & 3) * 2;
            float2 bc = *(const float2*)&g_bcat[c];
            float2 f0 = __half22float2(*reinterpret_cast<__half2*>(&d2[mf][nf][0]));
            float2 f1 = __half22float2(*reinterpret_cast<__half2*>(&d2[mf][nf][1]));
            float2 o0, o1;
            o0.x = d1[mf][nf][0] + (f0.x - d1[mf][nf][0]) * KINV + bc.x;
            o0.y = d1[mf][nf][1] + (f0.y - d1[mf][nf][1]) * KINV + bc.y;
            o1.x = d1[mf][nf][2] + (f1.x - d1[mf][nf][2]) * KINV + bc.x;
            o1.y = d1[mf][nf][3] + (f1.y - d1[mf][nf][3]) * KINV + bc.y;
            *(float2*)(g_Y + (size_t)r0 * NP + c) = o0;
            *(float2*)(g_Y + (size_t)(r0 + 8) * NP + c) = o1;
        }
    }
}

// ---------------------------------------------------------------------------
// K2 (persistent): fused rank-64 correction + masked mix.
// 296 CTAs (2/SM x 148), each statically iterates items (row-tile, agent).
// Hot loop = w1 groups 0..31; tail 33 (b1/elu), 34 (v1), 32 (w_final).
// ---------------------------------------------------------------------------
#define K2_GRID    296
#define K2_ITEMS   512
#define K2_OFF_W   18432
#define K2_WBUF    9216
#define K2_OFF_QS  36864
#define K2_OFF_RED 53760
#define K2_SMEM    (18432 + 18432 + 16896 + 1024)
__global__ __launch_bounds__(256, 2) void corr_mma(const float* __restrict__ qs,
                                                   const float* __restrict__ Wv2,
                                                   const float* __restrict__ bv2) {
    extern __shared__ char smem[];
    const uint32_t sbase = (uint32_t)__cvta_generic_to_shared(smem);
    __half* Sf  = (__half*)smem;                    // [128][72]
    __half* Wgf = (__half*)(smem + K2_OFF_W);       // [2][64][72]
    float* qs_s = (float*)(smem + K2_OFF_QS);       // [128][33]
    float* red  = (float*)(smem + K2_OFF_RED);      // [128][2]

    const int tid = threadIdx.x;
    const int lane = tid & 31;
    const int warp = tid >> 5;
    const int wm = warp & 3;
    const int wn = warp >> 2;
    const int wr = tid >> 3, wc8 = tid & 7;
    const int rloc0 = wm * 32 + (lane >> 2);
    const float bv2v = bv2[0];

    for (int item = blockIdx.x; item < K2_ITEMS; item += K2_GRID) {
        const int bt0 = (item & 15) * 128;
        const int ag  = item >> 4;
        const int yr0 = bt0 + wm * 32 + (lane >> 2);

        __syncthreads();   // previous item fully done before restaging

        // stage st chunk + qs tile
#pragma unroll
        for (int l = 0; l < 4; l++) {
            int idx = l * 256 + tid;
            int r = idx >> 3, c8 = idx & 7;
            *(uint4*)&Sf[r * 72 + c8 * 8] =
                *(const uint4*)(g_Sh + (size_t)(bt0 + r) * S_DIM + ag * 64 + c8 * 8);
        }
#pragma unroll
        for (int l = 0; l < 16; l++) {
            int idx = l * 256 + tid;
            int r = idx >> 5, c = idx & 31;
            qs_s[r * 33 + c] = qs[(size_t)(bt0 + r) * N_AG + c];
        }

        auto issueW = [&](int g, int b) {
#pragma unroll
            for (int l = 0; l < 2; l++) {
                int r = wr + l * 32;
                cp16(sbase + K2_OFF_W + b * K2_WBUF + (uint32_t)r * 144 + wc8 * 16,
                     g_Wh + (size_t)(ag * 64 + r) * NP + g * 64 + wc8 * 8);
            }
        };

        auto computeC = [&](const __half* WgfB, float (&c)[2][4][4]) {
#pragma unroll
            for (int mf = 0; mf < 2; mf++)
#pragma unroll
                for (int nf = 0; nf < 4; nf++)
#pragma unroll
                    for (int q = 0; q < 4; q++) c[mf][nf][q] = 0.f;
#pragma unroll
            for (int ks = 0; ks < 4; ks++) {
                uint32_t af[2][4];
#pragma unroll
                for (int mf = 0; mf < 2; mf++) {
                    const int ro = (wm * 32 + mf * 16 + (lane & 15)) * 72 + ks * 16 + (lane >> 4) * 8;
                    ldsm_x4(af[mf], &Sf[ro]);
                }
                uint32_t bf[4][2];
#pragma unroll
                for (int nq = 0; nq < 2; nq++) {
                    const int bo = (ks * 16 + (lane & 15)) * 72 + wn * 32 + nq * 16 + (lane >> 4) * 8;
                    uint32_t t[4];
                    ldsm_x4t(t, &WgfB[bo]);
                    bf[nq * 2][0] = t[0]; bf[nq * 2][1] = t[1];
                    bf[nq * 2 + 1][0] = t[2]; bf[nq * 2 + 1][1] = t[3];
                }
#pragma unroll
                for (int mf = 0; mf < 2; mf++)
#pragma unroll
                    for (int nf = 0; nf < 4; nf++)
                        mma_fp16(c[mf][nf], af[mf], bf[nf]);
            }
        };

        float h[4][8];
#pragma unroll
        for (int s = 0; s < 4; s++)
#pragma unroll
            for (int e = 0; e < 8; e++) h[s][e] = 0.f;
        float vp[4] = {0.f, 0.f, 0.f, 0.f};

        issueW(0, 0);
        CP_COMMIT();

        // ---- hot loop: w1 groups 0..31 ----
        for (int g = 0; g < 32; g++) {
            CP_WAIT(0);
            __syncthreads();
            issueW(g == 31 ? 33 : g + 1, (g + 1) & 1);
            CP_COMMIT();

            float c[2][4][4];
            computeC(Wgf + (g & 1) * 4608, c);

            float qv[4];
#pragma unroll
            for (int s = 0; s < 4; s++) {
                int rl = rloc0 + (s >> 1) * 16 + (s & 1) * 8;
                qv[s] = qs_s[rl * 33 + g];
            }
#pragma unroll
            for (int mf = 0; mf < 2; mf++) {
                int r0 = yr0 + mf * 16;
#pragma unroll
                for (int nf = 0; nf < 4; nf++) {
                    int col = g * 64 + wn * 32 + nf * 8 + (lane & 3) * 2;
                    float2 y0 = *(const float2*)(g_Y + (size_t)r0 * NP + col);
                    float2 y1 = *(const float2*)(g_Y + (size_t)(r0 + 8) * NP + col);
                    int s0 = mf * 2, s1 = mf * 2 + 1;
                    int e0 = nf * 2, e1 = nf * 2 + 1;
                    h[s0][e0] = fmaf(qv[s0], fabsf(y0.x - c[mf][nf][0]), h[s0][e0]);
                    h[s0][e1] = fmaf(qv[s0], fabsf(y0.y - c[mf][nf][1]), h[s0][e1]);
                    h[s1][e0] = fmaf(qv[s1], fabsf(y1.x - c[mf][nf][2]), h[s1][e0]);
                    h[s1][e1] = fmaf(qv[s1], fabsf(y1.y - c[mf][nf][3]), h[s1][e1]);
                }
            }
        }

        // ---- tail group 33 (b1): hidden = elu(h + m), buffer 0 ----
        CP_WAIT(0);
        __syncthreads();
        issueW(34, 1);
        CP_COMMIT();
        {
            float c[2][4][4];
            computeC(Wgf + 0 * 4608, c);
#pragma unroll
            for (int mf = 0; mf < 2; mf++) {
                int r0 = yr0 + mf * 16;
#pragma unroll
                for (int nf = 0; nf < 4; nf++) {
                    int col = 33 * 64 + wn * 32 + nf * 8 + (lane & 3) * 2;
                    float2 y0 = *(const float2*)(g_Y + (size_t)r0 * NP + col);
                    float2 y1 = *(const float2*)(g_Y + (size_t)(r0 + 8) * NP + col);
                    int s0 = mf * 2, s1 = mf * 2 + 1;
                    int e0 = nf * 2, e1 = nf * 2 + 1;
                    float t;
                    t = h[s0][e0] + (y0.x - c[mf][nf][0]); h[s0][e0] = t > 0.f ? t : expm1f(t);
                    t = h[s0][e1] + (y0.y - c[mf][nf][1]); h[s0][e1] = t > 0.f ? t : expm1f(t);
                    t = h[s1][e0] + (y1.x - c[mf][nf][2]); h[s1][e0] = t > 0.f ? t : expm1f(t);
                    t = h[s1][e1] + (y1.y - c[mf][nf][3]); h[s1][e1] = t > 0.f ? t : expm1f(t);
                }
            }
        }

        // ---- tail group 34 (v1): vp += relu(m) * Wv2, buffer 1 ----
        CP_WAIT(0);
        __syncthreads();
        issueW(32, 0);
        CP_COMMIT();
        {
            float c[2][4][4];
            computeC(Wgf + 1 * 4608, c);
#pragma unroll
            for (int mf = 0; mf < 2; mf++) {
                int r0 = yr0 + mf * 16;
#pragma unroll
                for (int nf = 0; nf < 4; nf++) {
                    int e = wn * 32 + nf * 8 + (lane & 3) * 2;
                    int col = 34 * 64 + e;
                    float2 y0 = *(const float2*)(g_Y + (size_t)r0 * NP + col);
                    float2 y1 = *(const float2*)(g_Y + (size_t)(r0 + 8) * NP + col);
                    float w0 = Wv2[e], w1 = Wv2[e + 1];
                    int s0 = mf * 2, s1 = mf * 2 + 1;
                    vp[s0] = fmaf(fmaxf(y0.x - c[mf][nf][0], 0.f), w0, vp[s0]);
                    vp[s0] = fmaf(fmaxf(y0.y - c[mf][nf][1], 0.f), w1, vp[s0]);
                    vp[s1] = fmaf(fmaxf(y1.x - c[mf][nf][2], 0.f), w0, vp[s1]);
                    vp[s1] = fmaf(fmaxf(y1.y - c[mf][nf][3], 0.f), w1, vp[s1]);
                }
            }
        }

        // ---- tail group 32 (w_final): s = vp + sum_e hidden * |m|, buffer 0 ----
        CP_WAIT(0);
        __syncthreads();
        float sacc[4] = { vp[0], vp[1], vp[2], vp[3] };
        {
            float c[2][4][4];
            computeC(Wgf + 0 * 4608, c);
#pragma unroll
            for (int mf = 0; mf < 2; mf++) {
                int r0 = yr0 + mf * 16;
#pragma unroll
                for (int nf = 0; nf < 4; nf++) {
                    int col = 32 * 64 + wn * 32 + nf * 8 + (lane & 3) * 2;
                    float2 y0 = *(const float2*)(g_Y + (size_t)r0 * NP + col);
                    float2 y1 = *(const float2*)(g_Y + (size_t)(r0 + 8) * NP + col);
                    int s0 = mf * 2, s1 = mf * 2 + 1;
                    int e0 = nf * 2, e1 = nf * 2 + 1;
                    sacc[s0] = fmaf(h[s0][e0], fabsf(y0.x - c[mf][nf][0]), sacc[s0]);
                    sacc[s0] = fmaf(h[s0][e1], fabsf(y0.y - c[mf][nf][1]), sacc[s0]);
                    sacc[s1] = fmaf(h[s1][e0], fabsf(y1.x - c[mf][nf][2]), sacc[s1]);
                    sacc[s1] = fmaf(h[s1][e1], fabsf(y1.y - c[mf][nf][3]), sacc[s1]);
                }
            }
        }

#pragma unroll
        for (int s = 0; s < 4; s++) {
            sacc[s] += __shfl_xor_sync(0xffffffffu, sacc[s], 1);
            sacc[s] += __shfl_xor_sync(0xffffffffu, sacc[s], 2);
        }
        if ((lane & 3) == 0) {
#pragma unroll
            for (int s = 0; s < 4; s++) {
                int rl = rloc0 + (s >> 1) * 16 + (s & 1) * 8;
                red[rl * 2 + wn] = sacc[s];
            }
        }
        __syncthreads();
        if (tid < 128)
            g_q1[(size_t)(bt0 + tid) * N_AG + ag] = red[tid * 2] + red[tid * 2 + 1] + bv2v;
    }
}

// ---------------------------------------------------------------------------
// K3: per-row epilogue (unchanged)
// ---------------------------------------------------------------------------
__global__ void final_kernel(const float* __restrict__ qs,
                             const float* __restrict__ Wv2,
                             const float* __restrict__ bv2,
                             float* __restrict__ out) {
    __shared__ float absY[2048];
    __shared__ float qs2[32];
    __shared__ float red[4];

    const int b = blockIdx.x;
    const int e = threadIdx.x;
    const int lane = e & 31, warp = e >> 5;
    const float* Yr = g_Y + (size_t)b * NP;

    float h = 0.f;
#pragma unroll
    for (int a = 0; a < 32; a++) {
        float v = fabsf(Yr[a * 64 + e]);
        absY[a * 64 + e] = v;
        h = fmaf(qs[(size_t)b * N_AG + a], v, h);
    }
    float wf = fabsf(Yr[2048 + e]);
    float b1 = Yr[2112 + e];
    float rv = fmaxf(Yr[2176 + e], 0.f) * Wv2[e];

    float t = h + b1;
    float hid = t > 0.f ? t : expm1f(t);
    float s = hid * wf;
    float sv = rv;
#pragma unroll
    for (int off = 16; off >= 1; off >>= 1) {
        s  += __shfl_xor_sync(0xffffffffu, s, off);
        sv += __shfl_xor_sync(0xffffffffu, sv, off);
    }
    if (lane == 0) { red[warp] = s; red[2 + warp] = sv; }
    __syncthreads();

    float vtot  = red[2] + red[3] + bv2[0];
    float q_tot = red[0] + red[1] + vtot;

    if (e < 32) {
        float d = fabsf(q_tot - g_q1[(size_t)b * N_AG + e]);
        float d2 = d * d;
#pragma unroll
        for (int off = 16; off >= 1; off >>= 1)
            d2 += __shfl_xor_sync(0xffffffffu, d2, off);
        float nrm = fmaxf(sqrtf(d2), 1e-12f);
        qs2[e] = qs[(size_t)b * N_AG + e] * (d / nrm);
    }
    __syncthreads();

    float h2 = 0.f;
#pragma unroll
    for (int a = 0; a < 32; a++)
        h2 = fmaf(qs2[a], absY[a * 64 + e], h2);
    float t2 = h2 + b1;
    float hid2 = t2 > 0.f ? t2 : expm1f(t2);
    float s2 = hid2 * wf;
#pragma unroll
    for (int off = 16; off >= 1; off >>= 1)
        s2 += __shfl_xor_sync(0xffffffffu, s2, off);
    if (lane == 0) red[warp] = s2;
    __syncthreads();
    if (e == 0) out[b] = red[0] + red[1] + vtot;
}

// ---------------------------------------------------------------------------
extern "C" void kernel_launch(void* const* d_in, const int* in_sizes, int n_in,
                              void* d_out, int out_size) {
    const float* agent_qs = (const float*)d_in[0];
    const float* states   = (const float*)d_in[1];
    const float* Ww1 = (const float*)d_in[2];
    const float* bw1 = (const float*)d_in[3];
    const float* Wwf = (const float*)d_in[4];
    const float* bwf = (const float*)d_in[5];
    const float* Wb1 = (const float*)d_in[6];
    const float* bb1 = (const float*)d_in[7];
    const float* Wv1 = (const float*)d_in[8];
    const float* bv1 = (const float*)d_in[9];
    const float* Wv2 = (const float*)d_in[10];
    const float* bv2 = (const float*)d_in[11];
    float* out = (float*)d_out;

    static bool attr_done = false;
    if (!attr_done) {
        cudaFuncSetAttribute(gemm_ka, cudaFuncAttributeMaxDynamicSharedMemorySize, K1_SMEM);
        cudaFuncSetAttribute(corr_mma, cudaFuncAttributeMaxDynamicSharedMemorySize, K2_SMEM);
        attr_done = true;
    }

    pack_kernel<<<512, 256>>>(states, Ww1, bw1, Wwf, bwf, Wb1, bb1, Wv1, bv1);
    gemm_ka<<<dim3(NP / 128, B_TOT / 128), 256, K1_SMEM>>>();
    corr_mma<<<K2_GRID, 256, K2_SMEM>>>(agent_qs, Wv2, bv2);
    final_kernel<<<B_TOT, 64>>>(agent_qs, Wv2, bv2, out);
}